// round 2
// baseline (speedup 1.0000x reference)
#include <cuda_runtime.h>
#include <cuda_bf16.h>
#include <math.h>

// Problem constants (fixed by the reference)
#define NMAX    50000
#define INCH    7
#define HID     64
#define HEADS   4
#define F1      (HEADS*HID)   // 256
#define OUTCH   6

// Scratch (static __device__ — allocation is forbidden). 16B-aligned for float4/red.v4.
__device__ __align__(16) float g_h1 [NMAX * F1];   // layer-1 features [N,256]
__device__ __align__(16) float g_al1[NMAX * 8];    // [al_src1[4], al_dst1[4]] per node
__device__ __align__(16) float g_acc1[NMAX * F1];  // unnormalized numerator layer 1
__device__ __align__(16) float g_den1[NMAX * 4];   // denominator per head
__device__ __align__(16) float g_h2 [NMAX * 8];    // [h2[6], al_src2, al_dst2] per node
__device__ __align__(16) float g_acc2[NMAX * 8];   // [num[6], den, junk] per node
__device__ int g_is64;                             // edge_index dtype flag

__device__ __forceinline__ void red4(float* p, float a, float b, float c, float d) {
    unsigned long long ga = __cvta_generic_to_global(p);
    asm volatile("red.global.add.v4.f32 [%0], {%1,%2,%3,%4};"
                 :: "l"(ga), "f"(a), "f"(b), "f"(c), "f"(d) : "memory");
}

__device__ __forceinline__ float lrelu(float v) { return v > 0.f ? v : 0.2f * v; }

__device__ __forceinline__ void get_edge(const void* ei, int E, int e, int& src, int& dst) {
    if (g_is64) {
        const long long* p = (const long long*)ei;
        src = (int)p[e]; dst = (int)p[E + e];
    } else {
        const int* p = (const int*)ei;
        src = p[e]; dst = p[E + e];
    }
}

// ---------------- Kernel 0: detect edge_index dtype ----------------
__global__ void k_detect(const void* ei, int E, int N) {
    if (threadIdx.x != 0 || blockIdx.x != 0) return;
    const long long* p = (const long long*)ei;
    int m = E < 256 ? E : 256;
    int ok = 1;
    for (int i = 0; i < m; i++) {
        long long v = p[i];
        if (v < 0 || v >= N) { ok = 0; break; }
    }
    g_is64 = ok;
}

// ---------------- Kernel 1: h1 = x@W1 ; attention logits ----------------
__global__ void __launch_bounds__(256) k_node1(
    const float* __restrict__ x, const float* __restrict__ W1,
    const float* __restrict__ a_src1, const float* __restrict__ a_dst1)
{
    int n = blockIdx.x;
    int t = threadIdx.x;           // 0..255
    __shared__ float xs[INCH];
    if (t < INCH) xs[t] = x[n * INCH + t];
    __syncthreads();

    float h = 0.f;
#pragma unroll
    for (int c = 0; c < INCH; c++) h = fmaf(xs[c], W1[c * F1 + t], h);
    g_h1[n * F1 + t] = h;

    int head = t >> 6, c = t & 63;
    __shared__ float rs[256], rd[256];
    rs[t] = h * a_src1[head * HID + c];
    rd[t] = h * a_dst1[head * HID + c];
    __syncthreads();
    // reduce within each 64-thread head group
    for (int s = 32; s >= 1; s >>= 1) {
        if (c < s) { rs[t] += rs[t + s]; rd[t] += rd[t + s]; }
        __syncthreads();
    }
    if (c == 0) {
        g_al1[n * 8 + head]     = rs[t];
        g_al1[n * 8 + 4 + head] = rd[t];
    }
}

// ---------------- Kernel 2 (HEAVY): layer-1 edge aggregation ----------------
// One warp per edge. Accumulates w*h1[src] into acc1[dst] and w into den1[dst].
__global__ void __launch_bounds__(256) k_edge1(
    const void* __restrict__ ei, int E, int N)
{
    int warp = (blockIdx.x * blockDim.x + threadIdx.x) >> 5;
    int lane = threadIdx.x & 31;
    int total = E + N;
    if (warp >= total) return;

    int src, dst;
    if (warp < E) get_edge(ei, E, warp, src, dst);
    else          src = dst = warp - E;

    const float4 s4 = *(const float4*)(g_al1 + src * 8);
    const float4 d4 = *(const float4*)(g_al1 + dst * 8 + 4);
    float w0 = __expf(lrelu(s4.x + d4.x));
    float w1 = __expf(lrelu(s4.y + d4.y));
    float w2 = __expf(lrelu(s4.z + d4.z));
    float w3 = __expf(lrelu(s4.w + d4.w));

    // lane handles float4 indices lane (heads 0/1) and lane+32 (heads 2/3)
    float wa = (lane < 16) ? w0 : w1;
    float wb = (lane < 16) ? w2 : w3;

    const float4* hs = (const float4*)(g_h1 + (size_t)src * F1);
    float*        oa = g_acc1 + (size_t)dst * F1;

    float4 v0 = hs[lane];
    float4 v1 = hs[lane + 32];
    red4(oa + lane * 4,        wa * v0.x, wa * v0.y, wa * v0.z, wa * v0.w);
    red4(oa + (lane + 32) * 4, wb * v1.x, wb * v1.y, wb * v1.z, wb * v1.w);
    if (lane == 0) red4(g_den1 + dst * 4, w0, w1, w2, w3);
}

// ---------------- Kernel 3: normalize, elu, h2 = h@W2, layer-2 logits ----------------
__global__ void __launch_bounds__(256) k_node2(
    const float* __restrict__ b1, const float* __restrict__ W2,
    const float* __restrict__ a_src2, const float* __restrict__ a_dst2)
{
    int n = blockIdx.x;
    int t = threadIdx.x;
    float den = g_den1[n * 4 + (t >> 6)];
    float v = g_acc1[n * F1 + t] / den + b1[t];
    v = v > 0.f ? v : expm1f(v);          // elu

    float z[OUTCH];
#pragma unroll
    for (int j = 0; j < OUTCH; j++) z[j] = v * W2[t * OUTCH + j];
#pragma unroll
    for (int j = 0; j < OUTCH; j++)
        for (int s = 16; s >= 1; s >>= 1) z[j] += __shfl_down_sync(0xffffffffu, z[j], s);

    __shared__ float sm[8][OUTCH];
    if ((t & 31) == 0) {
#pragma unroll
        for (int j = 0; j < OUTCH; j++) sm[t >> 5][j] = z[j];
    }
    __syncthreads();
    if (t == 0) {
        float y[OUTCH];
#pragma unroll
        for (int j = 0; j < OUTCH; j++) {
            float acc = 0.f;
#pragma unroll
            for (int w = 0; w < 8; w++) acc += sm[w][j];
            y[j] = acc;
        }
        float as = 0.f, ad = 0.f;
#pragma unroll
        for (int j = 0; j < OUTCH; j++) { as += y[j] * a_src2[j]; ad += y[j] * a_dst2[j]; }
        float* o = g_h2 + n * 8;
#pragma unroll
        for (int j = 0; j < OUTCH; j++) o[j] = y[j];
        o[6] = as;
        o[7] = ad;
    }
}

// ---------------- Kernel 4: layer-2 edge aggregation ----------------
__global__ void __launch_bounds__(256) k_edge2(
    const void* __restrict__ ei, int E, int N)
{
    int e = blockIdx.x * blockDim.x + threadIdx.x;
    int total = E + N;
    if (e >= total) return;

    int src, dst;
    if (e < E) get_edge(ei, E, e, src, dst);
    else       src = dst = e - E;

    const float4* hp = (const float4*)(g_h2 + (size_t)src * 8);
    float4 a = hp[0];                 // h2[0..3]
    float4 b = hp[1];                 // h2[4], h2[5], al_src2, al_dst2(of src, unused)
    float ald = g_h2[dst * 8 + 7];
    float w = __expf(lrelu(b.z + ald));

    float* o = g_acc2 + (size_t)dst * 8;
    red4(o,     w * a.x, w * a.y, w * a.z, w * a.w);
    red4(o + 4, w * b.x, w * b.y, w,       0.f);      // slots: num4, num5, den, junk
}

// ---------------- Kernel 5: finalize + log_softmax ----------------
__global__ void __launch_bounds__(256) k_final(
    const float* __restrict__ b2, float* __restrict__ out, int N)
{
    int n = blockIdx.x * blockDim.x + threadIdx.x;
    if (n >= N) return;
    const float* a = g_acc2 + (size_t)n * 8;
    float den = a[6];
    float y[OUTCH], mx = -1e30f;
#pragma unroll
    for (int j = 0; j < OUTCH; j++) {
        y[j] = a[j] / den + b2[j];
        mx = fmaxf(mx, y[j]);
    }
    float s = 0.f;
#pragma unroll
    for (int j = 0; j < OUTCH; j++) s += expf(y[j] - mx);
    float l = mx + logf(s);
#pragma unroll
    for (int j = 0; j < OUTCH; j++) out[n * OUTCH + j] = y[j] - l;
}

extern "C" void kernel_launch(void* const* d_in, const int* in_sizes, int n_in,
                              void* d_out, int out_size)
{
    const float* x      = (const float*)d_in[0];
    const void*  ei     = d_in[1];
    const float* W1     = (const float*)d_in[2];
    const float* a_src1 = (const float*)d_in[3];
    const float* a_dst1 = (const float*)d_in[4];
    const float* b1     = (const float*)d_in[5];
    const float* W2     = (const float*)d_in[6];
    const float* a_src2 = (const float*)d_in[7];
    const float* a_dst2 = (const float*)d_in[8];
    const float* b2     = (const float*)d_in[9];
    float*       out    = (float*)d_out;

    int N = in_sizes[0] / INCH;
    int E = in_sizes[1] / 2;
    int TE = E + N;

    // Zero accumulators (memset nodes are graph-capturable)
    void *p_acc1, *p_den1, *p_acc2;
    cudaGetSymbolAddress(&p_acc1, g_acc1);
    cudaGetSymbolAddress(&p_den1, g_den1);
    cudaGetSymbolAddress(&p_acc2, g_acc2);
    cudaMemsetAsync(p_acc1, 0, (size_t)N * F1 * sizeof(float), 0);
    cudaMemsetAsync(p_den1, 0, (size_t)N * 4 * sizeof(float), 0);
    cudaMemsetAsync(p_acc2, 0, (size_t)N * 8 * sizeof(float), 0);

    k_detect<<<1, 32>>>(ei, E, N);

    k_node1<<<N, 256>>>(x, W1, a_src1, a_dst1);

    {
        long long threads = (long long)TE * 32;
        int blocks = (int)((threads + 255) / 256);
        k_edge1<<<blocks, 256>>>(ei, E, N);
    }

    k_node2<<<N, 256>>>(b1, W2, a_src2, a_dst2);

    k_edge2<<<(TE + 255) / 256, 256>>>(ei, E, N);

    k_final<<<(N + 255) / 256, 256>>>(b2, out, N);
}

// round 3
// speedup vs baseline: 1.5492x; 1.5492x over previous
#include <cuda_runtime.h>
#include <cuda_bf16.h>
#include <math.h>

#define NMAX    50000
#define EMAX    1700000   // E + N upper bound
#define INCH    7
#define HID     64
#define HEADS   4
#define F1      (HEADS*HID)   // 256
#define OUTCH   6

// Scratch (static __device__ — allocation is forbidden)
__device__ __align__(16) float g_h1 [NMAX * F1];   // layer-1 features [N,256]
__device__ __align__(16) float g_al1[NMAX * 8];    // [al_src1[4], al_dst1[4]]
__device__ __align__(16) float g_acc1[NMAX * F1];  // layer-1 numerator (written once)
__device__ __align__(16) float g_den1[NMAX * 4];   // layer-1 denominator per head
__device__ __align__(16) float g_h2 [NMAX * 8];    // [h2[6], al_src2, al_dst2]
__device__ int g_cnt   [NMAX];
__device__ int g_offs  [NMAX + 1];
__device__ int g_cursor[NMAX];
__device__ int g_sorted[EMAX];                     // src ids grouped by dst
__device__ int g_is64;

__device__ __forceinline__ float lrelu(float v) { return v > 0.f ? v : 0.2f * v; }

__device__ __forceinline__ void get_edge(const void* ei, int E, int e, int& src, int& dst) {
    if (g_is64) {
        const long long* p = (const long long*)ei;
        src = (int)p[e]; dst = (int)p[E + e];
    } else {
        const int* p = (const int*)ei;
        src = p[e]; dst = p[E + e];
    }
}

__device__ __forceinline__ int get_dst(const void* ei, int E, int e) {
    if (g_is64) return (int)((const long long*)ei)[E + e];
    return ((const int*)ei)[E + e];
}

// ---------------- dtype detect ----------------
__global__ void k_detect(const void* ei, int E, int N) {
    if (threadIdx.x != 0 || blockIdx.x != 0) return;
    const long long* p = (const long long*)ei;
    int m = E < 256 ? E : 256;
    int ok = 1;
    for (int i = 0; i < m; i++) {
        long long v = p[i];
        if (v < 0 || v >= N) { ok = 0; break; }
    }
    g_is64 = ok;
}

// ---------------- CSR build: histogram ----------------
__global__ void k_hist(const void* __restrict__ ei, int E, int N) {
    int e = blockIdx.x * blockDim.x + threadIdx.x;
    int total = E + N;
    if (e >= total) return;
    int dst = (e < E) ? get_dst(ei, E, e) : (e - E);
    atomicAdd(&g_cnt[dst], 1);
}

// ---------------- CSR build: single-block scan ----------------
__global__ void __launch_bounds__(1024) k_scan(int N) {
    __shared__ int sums[1024];
    int t = threadIdx.x;
    int items = (N + 1023) >> 10;
    int start = t * items;
    int s = 0;
    for (int k = 0; k < items; k++) { int i = start + k; if (i < N) s += g_cnt[i]; }
    sums[t] = s; __syncthreads();
    for (int d = 1; d < 1024; d <<= 1) {
        int v = (t >= d) ? sums[t - d] : 0;
        __syncthreads();
        sums[t] += v;
        __syncthreads();
    }
    int run = t ? sums[t - 1] : 0;
    for (int k = 0; k < items; k++) {
        int i = start + k;
        if (i < N) { int c = g_cnt[i]; g_offs[i] = run; g_cursor[i] = run; run += c; }
    }
    if (t == 0) g_offs[N] = sums[1023];
}

// ---------------- CSR build: scatter ----------------
__global__ void k_scatter(const void* __restrict__ ei, int E, int N) {
    int e = blockIdx.x * blockDim.x + threadIdx.x;
    int total = E + N;
    if (e >= total) return;
    int src, dst;
    if (e < E) get_edge(ei, E, e, src, dst);
    else       src = dst = e - E;
    int pos = atomicAdd(&g_cursor[dst], 1);
    g_sorted[pos] = src;
}

// ---------------- node transform 1 (warp per node) ----------------
__global__ void __launch_bounds__(256) k_node1(
    const float* __restrict__ x, const float* __restrict__ W1,
    const float* __restrict__ a_src1, const float* __restrict__ a_dst1, int N)
{
    __shared__ float W1s[INCH * F1];
    __shared__ float as1[F1], ad1[F1];
    int tid = threadIdx.x;
    for (int i = tid; i < INCH * F1; i += 256) W1s[i] = W1[i];
    as1[tid] = a_src1[tid];
    ad1[tid] = a_dst1[tid];
    __syncthreads();

    int n = blockIdx.x * 8 + (tid >> 5);
    if (n >= N) return;
    int lane = tid & 31;
    int c0 = lane * 8;
    int head = lane >> 3;

    float xv = (lane < INCH) ? x[n * INCH + lane] : 0.f;
    float h[8];
#pragma unroll
    for (int j = 0; j < 8; j++) h[j] = 0.f;
#pragma unroll
    for (int i = 0; i < INCH; i++) {
        float xi = __shfl_sync(0xffffffffu, xv, i);
#pragma unroll
        for (int j = 0; j < 8; j++) h[j] = fmaf(xi, W1s[i * F1 + c0 + j], h[j]);
    }
    float4* hp = (float4*)(g_h1 + (size_t)n * F1 + c0);
    hp[0] = make_float4(h[0], h[1], h[2], h[3]);
    hp[1] = make_float4(h[4], h[5], h[6], h[7]);

    float ps = 0.f, pd = 0.f;
#pragma unroll
    for (int j = 0; j < 8; j++) {
        ps = fmaf(h[j], as1[c0 + j], ps);
        pd = fmaf(h[j], ad1[c0 + j], pd);
    }
#pragma unroll
    for (int s = 4; s >= 1; s >>= 1) {
        ps += __shfl_down_sync(0xffffffffu, ps, s, 8);
        pd += __shfl_down_sync(0xffffffffu, pd, s, 8);
    }
    if ((lane & 7) == 0) {
        g_al1[n * 8 + head]     = ps;
        g_al1[n * 8 + 4 + head] = pd;
    }
}

// ---------------- HEAVY: layer-1 aggregation (warp per dst, gather-only) ----------------
__global__ void __launch_bounds__(256) k_agg1(int N)
{
    int n = (blockIdx.x * blockDim.x + threadIdx.x) >> 5;
    if (n >= N) return;
    int lane = threadIdx.x & 31;
    int start = g_offs[n], end = g_offs[n + 1];

    const float4 d4 = *(const float4*)(g_al1 + (size_t)n * 8 + 4);  // uniform
    float4 acc0 = make_float4(0.f, 0.f, 0.f, 0.f);
    float4 acc1 = make_float4(0.f, 0.f, 0.f, 0.f);
    float den0 = 0.f, den1 = 0.f, den2 = 0.f, den3 = 0.f;

    for (int base = start; base < end; base += 32) {
        int cnt = min(32, end - base);
        int src = 0; float w0 = 0.f, w1 = 0.f, w2 = 0.f, w3 = 0.f;
        if (lane < cnt) {
            src = g_sorted[base + lane];
            float4 s4 = *(const float4*)(g_al1 + (size_t)src * 8);
            w0 = __expf(lrelu(s4.x + d4.x));
            w1 = __expf(lrelu(s4.y + d4.y));
            w2 = __expf(lrelu(s4.z + d4.z));
            w3 = __expf(lrelu(s4.w + d4.w));
            den0 += w0; den1 += w1; den2 += w2; den3 += w3;
        }
        for (int j = 0; j < cnt; j++) {
            int   sj = __shfl_sync(0xffffffffu, src, j);
            float a0 = __shfl_sync(0xffffffffu, w0, j);
            float a1 = __shfl_sync(0xffffffffu, w1, j);
            float a2 = __shfl_sync(0xffffffffu, w2, j);
            float a3 = __shfl_sync(0xffffffffu, w3, j);
            float wa = (lane < 16) ? a0 : a1;
            float wb = (lane < 16) ? a2 : a3;
            const float4* hs = (const float4*)(g_h1 + (size_t)sj * F1);
            float4 v0 = hs[lane];
            float4 v1 = hs[lane + 32];
            acc0.x = fmaf(wa, v0.x, acc0.x); acc0.y = fmaf(wa, v0.y, acc0.y);
            acc0.z = fmaf(wa, v0.z, acc0.z); acc0.w = fmaf(wa, v0.w, acc0.w);
            acc1.x = fmaf(wb, v1.x, acc1.x); acc1.y = fmaf(wb, v1.y, acc1.y);
            acc1.z = fmaf(wb, v1.z, acc1.z); acc1.w = fmaf(wb, v1.w, acc1.w);
        }
    }

    float4* oa = (float4*)(g_acc1 + (size_t)n * F1);
    oa[lane]      = acc0;
    oa[lane + 32] = acc1;
#pragma unroll
    for (int s = 16; s >= 1; s >>= 1) {
        den0 += __shfl_down_sync(0xffffffffu, den0, s);
        den1 += __shfl_down_sync(0xffffffffu, den1, s);
        den2 += __shfl_down_sync(0xffffffffu, den2, s);
        den3 += __shfl_down_sync(0xffffffffu, den3, s);
    }
    if (lane == 0)
        *(float4*)(g_den1 + (size_t)n * 4) = make_float4(den0, den1, den2, den3);
}

// ---------------- node transform 2 (warp per node) ----------------
__global__ void __launch_bounds__(256) k_node2(
    const float* __restrict__ b1, const float* __restrict__ W2,
    const float* __restrict__ a_src2, const float* __restrict__ a_dst2, int N)
{
    __shared__ float W2s[F1 * OUTCH];
    __shared__ float b1s[F1];
    int tid = threadIdx.x;
    for (int i = tid; i < F1 * OUTCH; i += 256) W2s[i] = W2[i];
    b1s[tid] = b1[tid];
    __syncthreads();

    int n = blockIdx.x * 8 + (tid >> 5);
    if (n >= N) return;
    int lane = tid & 31;
    int c0 = lane * 8;
    int head = lane >> 3;

    float inv = 1.f / g_den1[n * 4 + head];
    const float4* up = (const float4*)(g_acc1 + (size_t)n * F1 + c0);
    float4 u0 = up[0], u1 = up[1];
    float v[8] = {u0.x, u0.y, u0.z, u0.w, u1.x, u1.y, u1.z, u1.w};
    float z[OUTCH];
#pragma unroll
    for (int j = 0; j < OUTCH; j++) z[j] = 0.f;
#pragma unroll
    for (int k = 0; k < 8; k++) {
        float t = fmaf(v[k], inv, b1s[c0 + k]);
        t = t > 0.f ? t : expm1f(t);      // elu
#pragma unroll
        for (int j = 0; j < OUTCH; j++) z[j] = fmaf(t, W2s[(c0 + k) * OUTCH + j], z[j]);
    }
#pragma unroll
    for (int j = 0; j < OUTCH; j++)
#pragma unroll
        for (int s = 16; s >= 1; s >>= 1)
            z[j] += __shfl_down_sync(0xffffffffu, z[j], s);

    if (lane == 0) {
        float as = 0.f, ad = 0.f;
#pragma unroll
        for (int j = 0; j < OUTCH; j++) { as = fmaf(z[j], a_src2[j], as); ad = fmaf(z[j], a_dst2[j], ad); }
        float4* o = (float4*)(g_h2 + (size_t)n * 8);
        o[0] = make_float4(z[0], z[1], z[2], z[3]);
        o[1] = make_float4(z[4], z[5], as, ad);   // note: slot order [h4,h5,al_src,al_dst]
    }
}

// ---------------- layer-2 aggregation + log_softmax (warp per dst) ----------------
__global__ void __launch_bounds__(256) k_agg2(
    const float* __restrict__ b2, float* __restrict__ out, int N)
{
    int n = (blockIdx.x * blockDim.x + threadIdx.x) >> 5;
    if (n >= N) return;
    int lane = threadIdx.x & 31;
    int start = g_offs[n], end = g_offs[n + 1];

    float ald = g_h2[(size_t)n * 8 + 7];
    float acc[OUTCH] = {0.f, 0.f, 0.f, 0.f, 0.f, 0.f};
    float den = 0.f;

    for (int idx = start + lane; idx < end; idx += 32) {
        int src = g_sorted[idx];
        const float4* hp = (const float4*)(g_h2 + (size_t)src * 8);
        float4 a = hp[0];
        float4 b = hp[1];                  // [h4, h5, al_src, al_dst]
        float w = __expf(lrelu(b.z + ald));
        acc[0] = fmaf(w, a.x, acc[0]); acc[1] = fmaf(w, a.y, acc[1]);
        acc[2] = fmaf(w, a.z, acc[2]); acc[3] = fmaf(w, a.w, acc[3]);
        acc[4] = fmaf(w, b.x, acc[4]); acc[5] = fmaf(w, b.y, acc[5]);
        den += w;
    }
#pragma unroll
    for (int s = 16; s >= 1; s >>= 1) {
#pragma unroll
        for (int j = 0; j < OUTCH; j++) acc[j] += __shfl_down_sync(0xffffffffu, acc[j], s);
        den += __shfl_down_sync(0xffffffffu, den, s);
    }
    if (lane == 0) {
        float inv = 1.f / den;
        float y[OUTCH], mx = -1e30f;
#pragma unroll
        for (int j = 0; j < OUTCH; j++) {
            y[j] = fmaf(acc[j], inv, b2[j]);
            mx = fmaxf(mx, y[j]);
        }
        float s = 0.f;
#pragma unroll
        for (int j = 0; j < OUTCH; j++) s += expf(y[j] - mx);
        float l = mx + logf(s);
#pragma unroll
        for (int j = 0; j < OUTCH; j++) out[(size_t)n * OUTCH + j] = y[j] - l;
    }
}

extern "C" void kernel_launch(void* const* d_in, const int* in_sizes, int n_in,
                              void* d_out, int out_size)
{
    const float* x      = (const float*)d_in[0];
    const void*  ei     = d_in[1];
    const float* W1     = (const float*)d_in[2];
    const float* a_src1 = (const float*)d_in[3];
    const float* a_dst1 = (const float*)d_in[4];
    const float* b1     = (const float*)d_in[5];
    const float* W2     = (const float*)d_in[6];
    const float* a_src2 = (const float*)d_in[7];
    const float* a_dst2 = (const float*)d_in[8];
    const float* b2     = (const float*)d_in[9];
    float*       out    = (float*)d_out;

    int N  = in_sizes[0] / INCH;
    int E  = in_sizes[1] / 2;
    int TE = E + N;

    void* p_cnt;
    cudaGetSymbolAddress(&p_cnt, g_cnt);
    cudaMemsetAsync(p_cnt, 0, (size_t)N * sizeof(int), 0);

    k_detect<<<1, 32>>>(ei, E, N);
    k_node1<<<(N + 7) / 8, 256>>>(x, W1, a_src1, a_dst1, N);
    k_hist<<<(TE + 255) / 256, 256>>>(ei, E, N);
    k_scan<<<1, 1024>>>(N);
    k_scatter<<<(TE + 255) / 256, 256>>>(ei, E, N);
    k_agg1<<<(N * 32 + 255) / 256, 256>>>(N);
    k_node2<<<(N + 7) / 8, 256>>>(b1, W2, a_src2, a_dst2, N);
    k_agg2<<<(N * 32 + 255) / 256, 256>>>(b2, out, N);
}

// round 4
// speedup vs baseline: 2.1295x; 1.3746x over previous
#include <cuda_runtime.h>
#include <cuda_fp16.h>
#include <math.h>

#define NMAX    50000
#define EMAX    1700000   // E + N upper bound
#define INCH    7
#define HID     64
#define HEADS   4
#define F1      (HEADS*HID)   // 256
#define OUTCH   6
#define NB_MAX  256       // ceil(NMAX/256) = 196 <= 256

// Scratch (static __device__ — allocation is forbidden)
__device__ __align__(16) __half g_h1h[NMAX * F1]; // layer-1 features, fp16 [N,256]
__device__ __align__(16) float g_al1[NMAX * 8];   // [al_src1[4], al_dst1[4]] (fp32)
__device__ __align__(16) float g_acc1[NMAX * F1]; // layer-1 numerator (fp32, written once)
__device__ __align__(16) float g_den1[NMAX * 4];  // layer-1 denominator per head
__device__ __align__(16) float g_h2 [NMAX * 8];   // [h2[6], al_src2, al_dst2]
__device__ int g_cnt   [NMAX];
__device__ int g_offs  [NMAX + 1];
__device__ int g_cursor[NMAX];
__device__ int g_sorted[EMAX];                    // src ids grouped by dst
__device__ int g_bsum  [NB_MAX];
__device__ int g_boff  [NB_MAX];
__device__ int g_is64;

__device__ __forceinline__ float lrelu(float v) { return v > 0.f ? v : 0.2f * v; }

__device__ __forceinline__ void get_edge(const void* ei, int E, int e, int& src, int& dst) {
    if (g_is64) {
        const long long* p = (const long long*)ei;
        src = (int)p[e]; dst = (int)p[E + e];
    } else {
        const int* p = (const int*)ei;
        src = p[e]; dst = p[E + e];
    }
}

__device__ __forceinline__ int get_dst(const void* ei, int E, int e) {
    if (g_is64) return (int)((const long long*)ei)[E + e];
    return ((const int*)ei)[E + e];
}

// ---------------- dtype detect ----------------
__global__ void k_detect(const void* ei, int E, int N) {
    if (threadIdx.x != 0 || blockIdx.x != 0) return;
    const long long* p = (const long long*)ei;
    int m = E < 256 ? E : 256;
    int ok = 1;
    for (int i = 0; i < m; i++) {
        long long v = p[i];
        if (v < 0 || v >= N) { ok = 0; break; }
    }
    g_is64 = ok;
}

// ---------------- CSR build: histogram ----------------
__global__ void k_hist(const void* __restrict__ ei, int E, int N) {
    int e = blockIdx.x * blockDim.x + threadIdx.x;
    int total = E + N;
    if (e >= total) return;
    int dst = (e < E) ? get_dst(ei, E, e) : (e - E);
    atomicAdd(&g_cnt[dst], 1);
}

// ---------------- CSR scan phase A: per-block local exclusive scan ----------------
__global__ void __launch_bounds__(256) k_scanA(int N) {
    int b = blockIdx.x, t = threadIdx.x;
    int i = b * 256 + t;
    int c = (i < N) ? g_cnt[i] : 0;
    int v = c;
#pragma unroll
    for (int s = 1; s < 32; s <<= 1) {
        int u = __shfl_up_sync(0xffffffffu, v, s);
        if ((t & 31) >= s) v += u;
    }
    __shared__ int wsum[8];
    if ((t & 31) == 31) wsum[t >> 5] = v;
    __syncthreads();
    if (t == 0) {
        int run = 0;
#pragma unroll
        for (int w = 0; w < 8; w++) { int x = wsum[w]; wsum[w] = run; run += x; }
        g_bsum[b] = run;
    }
    __syncthreads();
    if (i < N) g_offs[i] = v - c + wsum[t >> 5];   // local exclusive prefix
}

// ---------------- CSR scan phase B: scan block partials (1 block) ----------------
__global__ void __launch_bounds__(256) k_scanB(int NB, int N) {
    int t = threadIdx.x;
    int c = (t < NB) ? g_bsum[t] : 0;
    int v = c;
#pragma unroll
    for (int s = 1; s < 32; s <<= 1) {
        int u = __shfl_up_sync(0xffffffffu, v, s);
        if ((t & 31) >= s) v += u;
    }
    __shared__ int wsum[8];
    if ((t & 31) == 31) wsum[t >> 5] = v;
    __syncthreads();
    if (t == 0) {
        int run = 0;
#pragma unroll
        for (int w = 0; w < 8; w++) { int x = wsum[w]; wsum[w] = run; run += x; }
    }
    __syncthreads();
    int incl = v + wsum[t >> 5];
    if (t < NB) g_boff[t] = incl - c;
    if (t == NB - 1) g_offs[N] = incl;
}

// ---------------- CSR scan phase C: apply block base + init cursor ----------------
__global__ void __launch_bounds__(256) k_scanC(int N) {
    int i = blockIdx.x * 256 + threadIdx.x;
    if (i >= N) return;
    int o = g_offs[i] + g_boff[blockIdx.x];
    g_offs[i] = o;
    g_cursor[i] = o;
}

// ---------------- CSR build: scatter ----------------
__global__ void k_scatter(const void* __restrict__ ei, int E, int N) {
    int e = blockIdx.x * blockDim.x + threadIdx.x;
    int total = E + N;
    if (e >= total) return;
    int src, dst;
    if (e < E) get_edge(ei, E, e, src, dst);
    else       src = dst = e - E;
    int pos = atomicAdd(&g_cursor[dst], 1);
    g_sorted[pos] = src;
}

// ---------------- node transform 1 (warp per node) ----------------
__global__ void __launch_bounds__(256) k_node1(
    const float* __restrict__ x, const float* __restrict__ W1,
    const float* __restrict__ a_src1, const float* __restrict__ a_dst1, int N)
{
    __shared__ float W1s[INCH * F1];
    __shared__ float as1[F1], ad1[F1];
    int tid = threadIdx.x;
    for (int i = tid; i < INCH * F1; i += 256) W1s[i] = W1[i];
    as1[tid] = a_src1[tid];
    ad1[tid] = a_dst1[tid];
    __syncthreads();

    int n = blockIdx.x * 8 + (tid >> 5);
    if (n >= N) return;
    int lane = tid & 31;
    int c0 = lane * 8;
    int head = lane >> 3;

    float xv = (lane < INCH) ? x[n * INCH + lane] : 0.f;
    float h[8];
#pragma unroll
    for (int j = 0; j < 8; j++) h[j] = 0.f;
#pragma unroll
    for (int i = 0; i < INCH; i++) {
        float xi = __shfl_sync(0xffffffffu, xv, i);
#pragma unroll
        for (int j = 0; j < 8; j++) h[j] = fmaf(xi, W1s[i * F1 + c0 + j], h[j]);
    }
    // store fp16 features (8 halfs = 16B per lane)
    union { __half2 q[4]; uint4 u; } pk;
#pragma unroll
    for (int j = 0; j < 4; j++) pk.q[j] = __floats2half2_rn(h[2 * j], h[2 * j + 1]);
    *(uint4*)(g_h1h + (size_t)n * F1 + c0) = pk.u;

    float ps = 0.f, pd = 0.f;
#pragma unroll
    for (int j = 0; j < 8; j++) {
        ps = fmaf(h[j], as1[c0 + j], ps);
        pd = fmaf(h[j], ad1[c0 + j], pd);
    }
#pragma unroll
    for (int s = 4; s >= 1; s >>= 1) {
        ps += __shfl_down_sync(0xffffffffu, ps, s, 8);
        pd += __shfl_down_sync(0xffffffffu, pd, s, 8);
    }
    if ((lane & 7) == 0) {
        g_al1[n * 8 + head]     = ps;
        g_al1[n * 8 + 4 + head] = pd;
    }
}

// ---------------- HEAVY: layer-1 aggregation (warp per dst, gather-only, fp16 feats) ----------------
__global__ void __launch_bounds__(256) k_agg1(int N)
{
    int n = (blockIdx.x * blockDim.x + threadIdx.x) >> 5;
    if (n >= N) return;
    int lane = threadIdx.x & 31;
    int start = g_offs[n], end = g_offs[n + 1];

    const float4 d4 = *(const float4*)(g_al1 + (size_t)n * 8 + 4);  // uniform
    float acc[8];
#pragma unroll
    for (int j = 0; j < 8; j++) acc[j] = 0.f;
    float den0 = 0.f, den1 = 0.f, den2 = 0.f, den3 = 0.f;

    for (int base = start; base < end; base += 32) {
        int cnt = min(32, end - base);
        int src = 0; float w0 = 0.f, w1 = 0.f, w2 = 0.f, w3 = 0.f;
        if (lane < cnt) {
            src = g_sorted[base + lane];
            float4 s4 = *(const float4*)(g_al1 + (size_t)src * 8);
            w0 = __expf(lrelu(s4.x + d4.x));
            w1 = __expf(lrelu(s4.y + d4.y));
            w2 = __expf(lrelu(s4.z + d4.z));
            w3 = __expf(lrelu(s4.w + d4.w));
            den0 += w0; den1 += w1; den2 += w2; den3 += w3;
        }
        for (int j = 0; j < cnt; j++) {
            int   sj = __shfl_sync(0xffffffffu, src, j);
            float a0 = __shfl_sync(0xffffffffu, w0, j);
            float a1 = __shfl_sync(0xffffffffu, w1, j);
            float a2 = __shfl_sync(0xffffffffu, w2, j);
            float a3 = __shfl_sync(0xffffffffu, w3, j);
            // lane covers channels lane*8..lane*8+7 -> head = lane>>3
            float w = (lane < 8) ? a0 : (lane < 16) ? a1 : (lane < 24) ? a2 : a3;
            union { uint4 u; __half2 q[4]; } pk;
            pk.u = *(const uint4*)(g_h1h + (size_t)sj * F1 + lane * 8);
#pragma unroll
            for (int k = 0; k < 4; k++) {
                float2 f = __half22float2(pk.q[k]);
                acc[2 * k]     = fmaf(w, f.x, acc[2 * k]);
                acc[2 * k + 1] = fmaf(w, f.y, acc[2 * k + 1]);
            }
        }
    }

    float4* oa = (float4*)(g_acc1 + (size_t)n * F1 + lane * 8);
    oa[0] = make_float4(acc[0], acc[1], acc[2], acc[3]);
    oa[1] = make_float4(acc[4], acc[5], acc[6], acc[7]);
#pragma unroll
    for (int s = 16; s >= 1; s >>= 1) {
        den0 += __shfl_down_sync(0xffffffffu, den0, s);
        den1 += __shfl_down_sync(0xffffffffu, den1, s);
        den2 += __shfl_down_sync(0xffffffffu, den2, s);
        den3 += __shfl_down_sync(0xffffffffu, den3, s);
    }
    if (lane == 0)
        *(float4*)(g_den1 + (size_t)n * 4) = make_float4(den0, den1, den2, den3);
}

// ---------------- node transform 2 (warp per node) ----------------
__global__ void __launch_bounds__(256) k_node2(
    const float* __restrict__ b1, const float* __restrict__ W2,
    const float* __restrict__ a_src2, const float* __restrict__ a_dst2, int N)
{
    __shared__ float W2s[F1 * OUTCH];
    __shared__ float b1s[F1];
    int tid = threadIdx.x;
    for (int i = tid; i < F1 * OUTCH; i += 256) W2s[i] = W2[i];
    b1s[tid] = b1[tid];
    __syncthreads();

    int n = blockIdx.x * 8 + (tid >> 5);
    if (n >= N) return;
    int lane = tid & 31;
    int c0 = lane * 8;
    int head = lane >> 3;

    float inv = 1.f / g_den1[n * 4 + head];
    const float4* up = (const float4*)(g_acc1 + (size_t)n * F1 + c0);
    float4 u0 = up[0], u1 = up[1];
    float v[8] = {u0.x, u0.y, u0.z, u0.w, u1.x, u1.y, u1.z, u1.w};
    float z[OUTCH];
#pragma unroll
    for (int j = 0; j < OUTCH; j++) z[j] = 0.f;
#pragma unroll
    for (int k = 0; k < 8; k++) {
        float t = fmaf(v[k], inv, b1s[c0 + k]);
        t = t > 0.f ? t : expm1f(t);      // elu
#pragma unroll
        for (int j = 0; j < OUTCH; j++) z[j] = fmaf(t, W2s[(c0 + k) * OUTCH + j], z[j]);
    }
#pragma unroll
    for (int j = 0; j < OUTCH; j++)
#pragma unroll
        for (int s = 16; s >= 1; s >>= 1)
            z[j] += __shfl_down_sync(0xffffffffu, z[j], s);

    if (lane == 0) {
        float as = 0.f, ad = 0.f;
#pragma unroll
        for (int j = 0; j < OUTCH; j++) { as = fmaf(z[j], a_src2[j], as); ad = fmaf(z[j], a_dst2[j], ad); }
        float4* o = (float4*)(g_h2 + (size_t)n * 8);
        o[0] = make_float4(z[0], z[1], z[2], z[3]);
        o[1] = make_float4(z[4], z[5], as, ad);   // slot order [h4,h5,al_src,al_dst]
    }
}

// ---------------- layer-2 aggregation + log_softmax (warp per dst) ----------------
__global__ void __launch_bounds__(256) k_agg2(
    const float* __restrict__ b2, float* __restrict__ out, int N)
{
    int n = (blockIdx.x * blockDim.x + threadIdx.x) >> 5;
    if (n >= N) return;
    int lane = threadIdx.x & 31;
    int start = g_offs[n], end = g_offs[n + 1];

    float ald = g_h2[(size_t)n * 8 + 7];
    float acc[OUTCH] = {0.f, 0.f, 0.f, 0.f, 0.f, 0.f};
    float den = 0.f;

    for (int idx = start + lane; idx < end; idx += 32) {
        int src = g_sorted[idx];
        const float4* hp = (const float4*)(g_h2 + (size_t)src * 8);
        float4 a = hp[0];
        float4 b = hp[1];                  // [h4, h5, al_src, al_dst]
        float w = __expf(lrelu(b.z + ald));
        acc[0] = fmaf(w, a.x, acc[0]); acc[1] = fmaf(w, a.y, acc[1]);
        acc[2] = fmaf(w, a.z, acc[2]); acc[3] = fmaf(w, a.w, acc[3]);
        acc[4] = fmaf(w, b.x, acc[4]); acc[5] = fmaf(w, b.y, acc[5]);
        den += w;
    }
#pragma unroll
    for (int s = 16; s >= 1; s >>= 1) {
#pragma unroll
        for (int j = 0; j < OUTCH; j++) acc[j] += __shfl_down_sync(0xffffffffu, acc[j], s);
        den += __shfl_down_sync(0xffffffffu, den, s);
    }
    if (lane == 0) {
        float inv = 1.f / den;
        float y[OUTCH], mx = -1e30f;
#pragma unroll
        for (int j = 0; j < OUTCH; j++) {
            y[j] = fmaf(acc[j], inv, b2[j]);
            mx = fmaxf(mx, y[j]);
        }
        float s = 0.f;
#pragma unroll
        for (int j = 0; j < OUTCH; j++) s += expf(y[j] - mx);
        float l = mx + logf(s);
#pragma unroll
        for (int j = 0; j < OUTCH; j++) out[(size_t)n * OUTCH + j] = y[j] - l;
    }
}

extern "C" void kernel_launch(void* const* d_in, const int* in_sizes, int n_in,
                              void* d_out, int out_size)
{
    const float* x      = (const float*)d_in[0];
    const void*  ei     = d_in[1];
    const float* W1     = (const float*)d_in[2];
    const float* a_src1 = (const float*)d_in[3];
    const float* a_dst1 = (const float*)d_in[4];
    const float* b1     = (const float*)d_in[5];
    const float* W2     = (const float*)d_in[6];
    const float* a_src2 = (const float*)d_in[7];
    const float* a_dst2 = (const float*)d_in[8];
    const float* b2     = (const float*)d_in[9];
    float*       out    = (float*)d_out;

    int N  = in_sizes[0] / INCH;
    int E  = in_sizes[1] / 2;
    int TE = E + N;
    int NB = (N + 255) / 256;

    void* p_cnt;
    cudaGetSymbolAddress(&p_cnt, g_cnt);
    cudaMemsetAsync(p_cnt, 0, (size_t)N * sizeof(int), 0);

    k_detect<<<1, 32>>>(ei, E, N);
    k_node1<<<(N + 7) / 8, 256>>>(x, W1, a_src1, a_dst1, N);
    k_hist<<<(TE + 255) / 256, 256>>>(ei, E, N);
    k_scanA<<<NB, 256>>>(N);
    k_scanB<<<1, 256>>>(NB, N);
    k_scanC<<<NB, 256>>>(N);
    k_scatter<<<(TE + 255) / 256, 256>>>(ei, E, N);
    k_agg1<<<(N * 32 + 255) / 256, 256>>>(N);
    k_node2<<<(N + 7) / 8, 256>>>(b1, W2, a_src2, a_dst2, N);
    k_agg2<<<(N * 32 + 255) / 256, 256>>>(b2, out, N);
}

// round 5
// speedup vs baseline: 2.3856x; 1.1202x over previous
#include <cuda_runtime.h>
#include <cuda_fp16.h>
#include <math.h>

#define NMAX    50000
#define EMAX    1700000   // E + N upper bound
#define INCH    7
#define HID     64
#define HEADS   4
#define F1      (HEADS*HID)   // 256
#define OUTCH   6
#define NB_MAX  256       // ceil(NMAX/256) = 196 <= 256

// Scratch (static __device__ — allocation is forbidden)
__device__ __align__(16) __half g_h1h[NMAX * F1]; // layer-1 features, fp16 [N,256]
__device__ __align__(16) float g_al1[NMAX * 8];   // [al_src1[4], al_dst1[4]] (fp32)
__device__ __align__(16) float g_h2 [NMAX * 8];   // [h2[6], al_src2, al_dst2]
__device__ int g_cnt   [NMAX];
__device__ int g_offs  [NMAX + 1];
__device__ int g_cursor[NMAX];
__device__ int g_sorted[EMAX];                    // src ids grouped by dst
__device__ int g_bsum  [NB_MAX];
__device__ int g_boff  [NB_MAX];
__device__ int g_is64;

__device__ __forceinline__ float lrelu(float v) { return v > 0.f ? v : 0.2f * v; }

__device__ __forceinline__ void get_edge(const void* ei, int E, int e, int& src, int& dst) {
    if (g_is64) {
        const long long* p = (const long long*)ei;
        src = (int)p[e]; dst = (int)p[E + e];
    } else {
        const int* p = (const int*)ei;
        src = p[e]; dst = p[E + e];
    }
}

__device__ __forceinline__ int get_dst(const void* ei, int E, int e) {
    if (g_is64) return (int)((const long long*)ei)[E + e];
    return ((const int*)ei)[E + e];
}

// ---------------- dtype detect ----------------
__global__ void k_detect(const void* ei, int E, int N) {
    if (threadIdx.x != 0 || blockIdx.x != 0) return;
    const long long* p = (const long long*)ei;
    int m = E < 256 ? E : 256;
    int ok = 1;
    for (int i = 0; i < m; i++) {
        long long v = p[i];
        if (v < 0 || v >= N) { ok = 0; break; }
    }
    g_is64 = ok;
}

// ---------------- CSR build: histogram ----------------
__global__ void k_hist(const void* __restrict__ ei, int E, int N) {
    int e = blockIdx.x * blockDim.x + threadIdx.x;
    int total = E + N;
    if (e >= total) return;
    int dst = (e < E) ? get_dst(ei, E, e) : (e - E);
    atomicAdd(&g_cnt[dst], 1);
}

// ---------------- CSR scan A: per-block local exclusive scan ----------------
__global__ void __launch_bounds__(256) k_scanA(int N) {
    int b = blockIdx.x, t = threadIdx.x;
    int i = b * 256 + t;
    int c = (i < N) ? g_cnt[i] : 0;
    int v = c;
#pragma unroll
    for (int s = 1; s < 32; s <<= 1) {
        int u = __shfl_up_sync(0xffffffffu, v, s);
        if ((t & 31) >= s) v += u;
    }
    __shared__ int wsum[8];
    if ((t & 31) == 31) wsum[t >> 5] = v;
    __syncthreads();
    if (t == 0) {
        int run = 0;
#pragma unroll
        for (int w = 0; w < 8; w++) { int x = wsum[w]; wsum[w] = run; run += x; }
        g_bsum[b] = run;
    }
    __syncthreads();
    if (i < N) g_offs[i] = v - c + wsum[t >> 5];
}

// ---------------- CSR scan B: scan block partials (1 block) ----------------
__global__ void __launch_bounds__(256) k_scanB(int NB, int N) {
    int t = threadIdx.x;
    int c = (t < NB) ? g_bsum[t] : 0;
    int v = c;
#pragma unroll
    for (int s = 1; s < 32; s <<= 1) {
        int u = __shfl_up_sync(0xffffffffu, v, s);
        if ((t & 31) >= s) v += u;
    }
    __shared__ int wsum[8];
    if ((t & 31) == 31) wsum[t >> 5] = v;
    __syncthreads();
    if (t == 0) {
        int run = 0;
#pragma unroll
        for (int w = 0; w < 8; w++) { int x = wsum[w]; wsum[w] = run; run += x; }
    }
    __syncthreads();
    int incl = v + wsum[t >> 5];
    if (t < NB) g_boff[t] = incl - c;
    if (t == NB - 1) g_offs[N] = incl;
}

// ---------------- CSR scan C: apply block base + init cursor ----------------
__global__ void __launch_bounds__(256) k_scanC(int N) {
    int i = blockIdx.x * 256 + threadIdx.x;
    if (i >= N) return;
    int o = g_offs[i] + g_boff[blockIdx.x];
    g_offs[i] = o;
    g_cursor[i] = o;
}

// ---------------- CSR build: scatter ----------------
__global__ void k_scatter(const void* __restrict__ ei, int E, int N) {
    int e = blockIdx.x * blockDim.x + threadIdx.x;
    int total = E + N;
    if (e >= total) return;
    int src, dst;
    if (e < E) get_edge(ei, E, e, src, dst);
    else       src = dst = e - E;
    int pos = atomicAdd(&g_cursor[dst], 1);
    g_sorted[pos] = src;
}

// ---------------- node transform 1 (warp per node) ----------------
__global__ void __launch_bounds__(256) k_node1(
    const float* __restrict__ x, const float* __restrict__ W1,
    const float* __restrict__ a_src1, const float* __restrict__ a_dst1, int N)
{
    __shared__ float W1s[INCH * F1];
    __shared__ float as1[F1], ad1[F1];
    int tid = threadIdx.x;
    for (int i = tid; i < INCH * F1; i += 256) W1s[i] = W1[i];
    as1[tid] = a_src1[tid];
    ad1[tid] = a_dst1[tid];
    __syncthreads();

    int n = blockIdx.x * 8 + (tid >> 5);
    if (n >= N) return;
    int lane = tid & 31;
    int c0 = lane * 8;
    int head = lane >> 3;

    float xv = (lane < INCH) ? x[n * INCH + lane] : 0.f;
    float h[8];
#pragma unroll
    for (int j = 0; j < 8; j++) h[j] = 0.f;
#pragma unroll
    for (int i = 0; i < INCH; i++) {
        float xi = __shfl_sync(0xffffffffu, xv, i);
#pragma unroll
        for (int j = 0; j < 8; j++) h[j] = fmaf(xi, W1s[i * F1 + c0 + j], h[j]);
    }
    union { __half2 q[4]; uint4 u; } pk;
#pragma unroll
    for (int j = 0; j < 4; j++) pk.q[j] = __floats2half2_rn(h[2 * j], h[2 * j + 1]);
    *(uint4*)(g_h1h + (size_t)n * F1 + c0) = pk.u;

    float ps = 0.f, pd = 0.f;
#pragma unroll
    for (int j = 0; j < 8; j++) {
        ps = fmaf(h[j], as1[c0 + j], ps);
        pd = fmaf(h[j], ad1[c0 + j], pd);
    }
#pragma unroll
    for (int s = 4; s >= 1; s >>= 1) {
        ps += __shfl_down_sync(0xffffffffu, ps, s, 8);
        pd += __shfl_down_sync(0xffffffffu, pd, s, 8);
    }
    if ((lane & 7) == 0) {
        g_al1[n * 8 + head]     = ps;
        g_al1[n * 8 + 4 + head] = pd;
    }
}

// ---------------- FUSED HEAVY: layer-1 aggregation + normalize + elu + @W2 + layer-2 logits ----------------
// Warp per dst node. Numerator lives in registers; no acc1 round-trip.
__global__ void __launch_bounds__(256) k_agg1n2(
    const float* __restrict__ b1, const float* __restrict__ W2,
    const float* __restrict__ a_src2, const float* __restrict__ a_dst2, int N)
{
    __shared__ float W2s[F1 * OUTCH];   // 6 KB
    __shared__ float b1s[F1];
    __shared__ float as2[OUTCH], ad2[OUTCH];
    int tid = threadIdx.x;
    for (int i = tid; i < F1 * OUTCH; i += 256) W2s[i] = W2[i];
    b1s[tid] = b1[tid];
    if (tid < OUTCH) { as2[tid] = a_src2[tid]; ad2[tid] = a_dst2[tid]; }
    __syncthreads();

    int n = (blockIdx.x * blockDim.x + tid) >> 5;
    if (n >= N) return;
    int lane = tid & 31;
    int c0 = lane * 8;
    int head = lane >> 3;
    int start = g_offs[n], end = g_offs[n + 1];

    const float4 d4 = *(const float4*)(g_al1 + (size_t)n * 8 + 4);  // uniform
    float acc[8];
#pragma unroll
    for (int j = 0; j < 8; j++) acc[j] = 0.f;
    float den0 = 0.f, den1 = 0.f, den2 = 0.f, den3 = 0.f;

    for (int base = start; base < end; base += 32) {
        int cnt = min(32, end - base);
        int src = 0; float w0 = 0.f, w1 = 0.f, w2 = 0.f, w3 = 0.f;
        if (lane < cnt) {
            src = g_sorted[base + lane];
            float4 s4 = *(const float4*)(g_al1 + (size_t)src * 8);
            w0 = __expf(lrelu(s4.x + d4.x));
            w1 = __expf(lrelu(s4.y + d4.y));
            w2 = __expf(lrelu(s4.z + d4.z));
            w3 = __expf(lrelu(s4.w + d4.w));
            den0 += w0; den1 += w1; den2 += w2; den3 += w3;
        }
        for (int j = 0; j < cnt; j++) {
            int   sj = __shfl_sync(0xffffffffu, src, j);
            float a0 = __shfl_sync(0xffffffffu, w0, j);
            float a1 = __shfl_sync(0xffffffffu, w1, j);
            float a2 = __shfl_sync(0xffffffffu, w2, j);
            float a3 = __shfl_sync(0xffffffffu, w3, j);
            float w = (lane < 8) ? a0 : (lane < 16) ? a1 : (lane < 24) ? a2 : a3;
            union { uint4 u; __half2 q[4]; } pk;
            pk.u = *(const uint4*)(g_h1h + (size_t)sj * F1 + c0);
#pragma unroll
            for (int k = 0; k < 4; k++) {
                float2 f = __half22float2(pk.q[k]);
                acc[2 * k]     = fmaf(w, f.x, acc[2 * k]);
                acc[2 * k + 1] = fmaf(w, f.y, acc[2 * k + 1]);
            }
        }
    }

    // reduce denominators (per head), broadcast back
#pragma unroll
    for (int s = 16; s >= 1; s >>= 1) {
        den0 += __shfl_down_sync(0xffffffffu, den0, s);
        den1 += __shfl_down_sync(0xffffffffu, den1, s);
        den2 += __shfl_down_sync(0xffffffffu, den2, s);
        den3 += __shfl_down_sync(0xffffffffu, den3, s);
    }
    den0 = __shfl_sync(0xffffffffu, den0, 0);
    den1 = __shfl_sync(0xffffffffu, den1, 0);
    den2 = __shfl_sync(0xffffffffu, den2, 0);
    den3 = __shfl_sync(0xffffffffu, den3, 0);
    float inv = 1.f / ((head == 0) ? den0 : (head == 1) ? den1 : (head == 2) ? den2 : den3);

    // normalize, +b1, elu, multiply into W2 (per-lane partials over its 8 channels)
    float z[OUTCH];
#pragma unroll
    for (int j = 0; j < OUTCH; j++) z[j] = 0.f;
#pragma unroll
    for (int k = 0; k < 8; k++) {
        float t = fmaf(acc[k], inv, b1s[c0 + k]);
        t = t > 0.f ? t : expm1f(t);      // elu
#pragma unroll
        for (int j = 0; j < OUTCH; j++) z[j] = fmaf(t, W2s[(c0 + k) * OUTCH + j], z[j]);
    }
#pragma unroll
    for (int j = 0; j < OUTCH; j++)
#pragma unroll
        for (int s = 16; s >= 1; s >>= 1)
            z[j] += __shfl_down_sync(0xffffffffu, z[j], s);

    if (lane == 0) {
        float as = 0.f, ad = 0.f;
#pragma unroll
        for (int j = 0; j < OUTCH; j++) { as = fmaf(z[j], as2[j], as); ad = fmaf(z[j], ad2[j], ad); }
        float4* o = (float4*)(g_h2 + (size_t)n * 8);
        o[0] = make_float4(z[0], z[1], z[2], z[3]);
        o[1] = make_float4(z[4], z[5], as, ad);   // [h4, h5, al_src2, al_dst2]
    }
}

// ---------------- layer-2 aggregation + log_softmax (8 lanes per dst) ----------------
__global__ void __launch_bounds__(256) k_agg2(
    const float* __restrict__ b2, float* __restrict__ out, int N)
{
    int g = (blockIdx.x * blockDim.x + threadIdx.x) >> 3;   // subwarp index
    if (g >= N) return;
    int n = g;
    int sl = threadIdx.x & 7;
    int start = g_offs[n], end = g_offs[n + 1];

    float ald = g_h2[(size_t)n * 8 + 7];
    float acc[OUTCH] = {0.f, 0.f, 0.f, 0.f, 0.f, 0.f};
    float den = 0.f;

    for (int idx = start + sl; idx < end; idx += 8) {
        int src = g_sorted[idx];
        const float4* hp = (const float4*)(g_h2 + (size_t)src * 8);
        float4 a = hp[0];
        float4 b = hp[1];                  // [h4, h5, al_src, al_dst]
        float w = __expf(lrelu(b.z + ald));
        acc[0] = fmaf(w, a.x, acc[0]); acc[1] = fmaf(w, a.y, acc[1]);
        acc[2] = fmaf(w, a.z, acc[2]); acc[3] = fmaf(w, a.w, acc[3]);
        acc[4] = fmaf(w, b.x, acc[4]); acc[5] = fmaf(w, b.y, acc[5]);
        den += w;
    }
#pragma unroll
    for (int s = 4; s >= 1; s >>= 1) {
#pragma unroll
        for (int j = 0; j < OUTCH; j++) acc[j] += __shfl_down_sync(0xffffffffu, acc[j], s, 8);
        den += __shfl_down_sync(0xffffffffu, den, s, 8);
    }
    if (sl == 0) {
        float inv = 1.f / den;
        float y[OUTCH], mx = -1e30f;
#pragma unroll
        for (int j = 0; j < OUTCH; j++) {
            y[j] = fmaf(acc[j], inv, b2[j]);
            mx = fmaxf(mx, y[j]);
        }
        float s = 0.f;
#pragma unroll
        for (int j = 0; j < OUTCH; j++) s += expf(y[j] - mx);
        float l = mx + logf(s);
#pragma unroll
        for (int j = 0; j < OUTCH; j++) out[(size_t)n * OUTCH + j] = y[j] - l;
    }
}

extern "C" void kernel_launch(void* const* d_in, const int* in_sizes, int n_in,
                              void* d_out, int out_size)
{
    const float* x      = (const float*)d_in[0];
    const void*  ei     = d_in[1];
    const float* W1     = (const float*)d_in[2];
    const float* a_src1 = (const float*)d_in[3];
    const float* a_dst1 = (const float*)d_in[4];
    const float* b1     = (const float*)d_in[5];
    const float* W2     = (const float*)d_in[6];
    const float* a_src2 = (const float*)d_in[7];
    const float* a_dst2 = (const float*)d_in[8];
    const float* b2     = (const float*)d_in[9];
    float*       out    = (float*)d_out;

    int N  = in_sizes[0] / INCH;
    int E  = in_sizes[1] / 2;
    int TE = E + N;
    int NB = (N + 255) / 256;

    void* p_cnt;
    cudaGetSymbolAddress(&p_cnt, g_cnt);
    cudaMemsetAsync(p_cnt, 0, (size_t)N * sizeof(int), 0);

    k_detect<<<1, 32>>>(ei, E, N);
    k_node1<<<(N + 7) / 8, 256>>>(x, W1, a_src1, a_dst1, N);
    k_hist<<<(TE + 255) / 256, 256>>>(ei, E, N);
    k_scanA<<<NB, 256>>>(N);
    k_scanB<<<1, 256>>>(NB, N);
    k_scanC<<<NB, 256>>>(N);
    k_scatter<<<(TE + 255) / 256, 256>>>(ei, E, N);
    k_agg1n2<<<(N * 32 + 255) / 256, 256>>>(b1, W2, a_src2, a_dst2, N);
    k_agg2<<<(N * 8 + 255) / 256, 256>>>(b2, out, N);
}

// round 6
// speedup vs baseline: 2.7014x; 1.1324x over previous
#include <cuda_runtime.h>
#include <cuda_fp16.h>
#include <math.h>

#define NMAX    50000
#define EMAX    1700000   // E + N upper bound
#define INCH    7
#define HID     64
#define HEADS   4
#define F1      (HEADS*HID)   // 256
#define OUTCH   6
#define NB_MAX  256       // ceil(NMAX/256) = 196 <= 256

// Scratch (static __device__ — allocation is forbidden)
__device__ __align__(16) unsigned char g_h1q[NMAX * F1]; // layer-1 features, fp8 e4m3 [N,256]
__device__ __align__(16) float g_al1[NMAX * 8];   // [al_src1[4], al_dst1[4]] (fp32)
__device__ __align__(16) float g_h2 [NMAX * 8];   // [h2[6], al_src2, al_dst2]
__device__ int g_cnt   [NMAX];
__device__ int g_offs  [NMAX + 1];
__device__ int g_cursor[NMAX];
__device__ int g_sorted[EMAX];                    // src ids grouped by dst
__device__ int g_src32 [EMAX];
__device__ int g_dst32 [EMAX];
__device__ int g_bsum  [NB_MAX];
__device__ int g_boff  [NB_MAX];
__device__ int g_is64;

__device__ __forceinline__ float lrelu(float v) { return v > 0.f ? v : 0.2f * v; }

// pack two floats -> 2x e4m3 (byte0 = lo, byte1 = hi)
__device__ __forceinline__ unsigned short pack_e4m3(float lo, float hi) {
    unsigned short r;
    asm("cvt.rn.satfinite.e4m3x2.f32 %0, %1, %2;" : "=h"(r) : "f"(hi), "f"(lo));
    return r;
}
// unpack 2x e4m3 -> float2 (.x = byte0, .y = byte1)
__device__ __forceinline__ float2 unpack_e4m3(unsigned short v) {
    unsigned int h;
    asm("cvt.rn.f16x2.e4m3x2 %0, %1;" : "=r"(h) : "h"(v));
    __half2 hh = *(__half2*)&h;
    return __half22float2(hh);
}

__device__ __forceinline__ void get_edge64(const void* ei, int E, int e, int& src, int& dst) {
    if (g_is64) {
        const long long* p = (const long long*)ei;
        src = (int)p[e]; dst = (int)p[E + e];
    } else {
        const int* p = (const int*)ei;
        src = p[e]; dst = p[E + e];
    }
}

// ---------------- dtype detect ----------------
__global__ void k_detect(const void* ei, int E, int N) {
    if (threadIdx.x != 0 || blockIdx.x != 0) return;
    const long long* p = (const long long*)ei;
    int m = E < 256 ? E : 256;
    int ok = 1;
    for (int i = 0; i < m; i++) {
        long long v = p[i];
        if (v < 0 || v >= N) { ok = 0; break; }
    }
    g_is64 = ok;
}

// ---------------- CSR build: histogram + int32 conversion ----------------
__global__ void k_hist(const void* __restrict__ ei, int E, int N) {
    int e = blockIdx.x * blockDim.x + threadIdx.x;
    int total = E + N;
    if (e >= total) return;
    int dst;
    if (e < E) {
        int src;
        get_edge64(ei, E, e, src, dst);
        g_src32[e] = src;
        g_dst32[e] = dst;
    } else {
        dst = e - E;
    }
    atomicAdd(&g_cnt[dst], 1);
}

// ---------------- CSR scan A: per-block local exclusive scan ----------------
__global__ void __launch_bounds__(256) k_scanA(int N) {
    int b = blockIdx.x, t = threadIdx.x;
    int i = b * 256 + t;
    int c = (i < N) ? g_cnt[i] : 0;
    int v = c;
#pragma unroll
    for (int s = 1; s < 32; s <<= 1) {
        int u = __shfl_up_sync(0xffffffffu, v, s);
        if ((t & 31) >= s) v += u;
    }
    __shared__ int wsum[8];
    if ((t & 31) == 31) wsum[t >> 5] = v;
    __syncthreads();
    if (t == 0) {
        int run = 0;
#pragma unroll
        for (int w = 0; w < 8; w++) { int x = wsum[w]; wsum[w] = run; run += x; }
        g_bsum[b] = run;
    }
    __syncthreads();
    if (i < N) g_offs[i] = v - c + wsum[t >> 5];
}

// ---------------- CSR scan B: scan block partials (1 block) ----------------
__global__ void __launch_bounds__(256) k_scanB(int NB, int N) {
    int t = threadIdx.x;
    int c = (t < NB) ? g_bsum[t] : 0;
    int v = c;
#pragma unroll
    for (int s = 1; s < 32; s <<= 1) {
        int u = __shfl_up_sync(0xffffffffu, v, s);
        if ((t & 31) >= s) v += u;
    }
    __shared__ int wsum[8];
    if ((t & 31) == 31) wsum[t >> 5] = v;
    __syncthreads();
    if (t == 0) {
        int run = 0;
#pragma unroll
        for (int w = 0; w < 8; w++) { int x = wsum[w]; wsum[w] = run; run += x; }
    }
    __syncthreads();
    int incl = v + wsum[t >> 5];
    if (t < NB) g_boff[t] = incl - c;
    if (t == NB - 1) g_offs[N] = incl;
}

// ---------------- CSR scan C: apply block base + init cursor ----------------
__global__ void __launch_bounds__(256) k_scanC(int N) {
    int i = blockIdx.x * 256 + threadIdx.x;
    if (i >= N) return;
    int o = g_offs[i] + g_boff[blockIdx.x];
    g_offs[i] = o;
    g_cursor[i] = o;
}

// ---------------- CSR build: scatter ----------------
__global__ void k_scatter(int E, int N) {
    int e = blockIdx.x * blockDim.x + threadIdx.x;
    int total = E + N;
    if (e >= total) return;
    int src, dst;
    if (e < E) { src = g_src32[e]; dst = g_dst32[e]; }
    else       { src = dst = e - E; }
    int pos = atomicAdd(&g_cursor[dst], 1);
    g_sorted[pos] = src;
}

// ---------------- node transform 1 (warp per node) ----------------
__global__ void __launch_bounds__(256) k_node1(
    const float* __restrict__ x, const float* __restrict__ W1,
    const float* __restrict__ a_src1, const float* __restrict__ a_dst1, int N)
{
    __shared__ float W1s[INCH * F1];
    __shared__ float as1[F1], ad1[F1];
    int tid = threadIdx.x;
    for (int i = tid; i < INCH * F1; i += 256) W1s[i] = W1[i];
    as1[tid] = a_src1[tid];
    ad1[tid] = a_dst1[tid];
    __syncthreads();

    int n = blockIdx.x * 8 + (tid >> 5);
    if (n >= N) return;
    int lane = tid & 31;
    int c0 = lane * 8;
    int head = lane >> 3;

    float xv = (lane < INCH) ? x[n * INCH + lane] : 0.f;
    float h[8];
#pragma unroll
    for (int j = 0; j < 8; j++) h[j] = 0.f;
#pragma unroll
    for (int i = 0; i < INCH; i++) {
        float xi = __shfl_sync(0xffffffffu, xv, i);
#pragma unroll
        for (int j = 0; j < 8; j++) h[j] = fmaf(xi, W1s[i * F1 + c0 + j], h[j]);
    }
    // store fp8 features (8 bytes per lane)
    unsigned short p0 = pack_e4m3(h[0], h[1]);
    unsigned short p1 = pack_e4m3(h[2], h[3]);
    unsigned short p2 = pack_e4m3(h[4], h[5]);
    unsigned short p3 = pack_e4m3(h[6], h[7]);
    uint2 pk;
    pk.x = (unsigned)p0 | ((unsigned)p1 << 16);
    pk.y = (unsigned)p2 | ((unsigned)p3 << 16);
    *(uint2*)(g_h1q + (size_t)n * F1 + c0) = pk;

    float ps = 0.f, pd = 0.f;
#pragma unroll
    for (int j = 0; j < 8; j++) {
        ps = fmaf(h[j], as1[c0 + j], ps);
        pd = fmaf(h[j], ad1[c0 + j], pd);
    }
#pragma unroll
    for (int s = 4; s >= 1; s >>= 1) {
        ps += __shfl_down_sync(0xffffffffu, ps, s, 8);
        pd += __shfl_down_sync(0xffffffffu, pd, s, 8);
    }
    if ((lane & 7) == 0) {
        g_al1[n * 8 + head]     = ps;
        g_al1[n * 8 + 4 + head] = pd;
    }
}

// ---------------- FUSED HEAVY: layer-1 agg + normalize + elu + @W2 + layer-2 logits ----------------
__global__ void __launch_bounds__(256) k_agg1n2(
    const float* __restrict__ b1, const float* __restrict__ W2,
    const float* __restrict__ a_src2, const float* __restrict__ a_dst2, int N)
{
    __shared__ float W2s[F1 * OUTCH];   // 6 KB
    __shared__ float b1s[F1];
    __shared__ float as2[OUTCH], ad2[OUTCH];
    __shared__ int    ssrc[8][32];
    __shared__ float4 sww [8][32];
    int tid = threadIdx.x;
    for (int i = tid; i < F1 * OUTCH; i += 256) W2s[i] = W2[i];
    b1s[tid] = b1[tid];
    if (tid < OUTCH) { as2[tid] = a_src2[tid]; ad2[tid] = a_dst2[tid]; }
    __syncthreads();

    int n = (blockIdx.x * blockDim.x + tid) >> 5;
    if (n >= N) return;
    int lane = tid & 31;
    int wrp = tid >> 5;
    int c0 = lane * 8;
    int head = lane >> 3;
    int start = g_offs[n], end = g_offs[n + 1];

    const float4 d4 = *(const float4*)(g_al1 + (size_t)n * 8 + 4);  // uniform
    float acc[8];
#pragma unroll
    for (int j = 0; j < 8; j++) acc[j] = 0.f;
    float den0 = 0.f, den1 = 0.f, den2 = 0.f, den3 = 0.f;

    for (int base = start; base < end; base += 32) {
        int cnt = min(32, end - base);
        if (lane < cnt) {
            int s = g_sorted[base + lane];
            float4 s4 = *(const float4*)(g_al1 + (size_t)s * 8);
            float w0 = __expf(lrelu(s4.x + d4.x));
            float w1 = __expf(lrelu(s4.y + d4.y));
            float w2 = __expf(lrelu(s4.z + d4.z));
            float w3 = __expf(lrelu(s4.w + d4.w));
            den0 += w0; den1 += w1; den2 += w2; den3 += w3;
            ssrc[wrp][lane] = s;
            sww [wrp][lane] = make_float4(w0, w1, w2, w3);
        }
        __syncwarp();
        int j = 0;
        for (; j + 2 <= cnt; j += 2) {
            int sA = ssrc[wrp][j];
            int sB = ssrc[wrp][j + 1];
            uint2 rA = *(const uint2*)(g_h1q + (size_t)sA * F1 + c0);
            uint2 rB = *(const uint2*)(g_h1q + (size_t)sB * F1 + c0);
            float wA = ((const float*)&sww[wrp][j    ])[head];
            float wB = ((const float*)&sww[wrp][j + 1])[head];
            {
                float2 f0 = unpack_e4m3((unsigned short)(rA.x & 0xffff));
                float2 f1 = unpack_e4m3((unsigned short)(rA.x >> 16));
                float2 f2 = unpack_e4m3((unsigned short)(rA.y & 0xffff));
                float2 f3 = unpack_e4m3((unsigned short)(rA.y >> 16));
                acc[0] = fmaf(wA, f0.x, acc[0]); acc[1] = fmaf(wA, f0.y, acc[1]);
                acc[2] = fmaf(wA, f1.x, acc[2]); acc[3] = fmaf(wA, f1.y, acc[3]);
                acc[4] = fmaf(wA, f2.x, acc[4]); acc[5] = fmaf(wA, f2.y, acc[5]);
                acc[6] = fmaf(wA, f3.x, acc[6]); acc[7] = fmaf(wA, f3.y, acc[7]);
            }
            {
                float2 f0 = unpack_e4m3((unsigned short)(rB.x & 0xffff));
                float2 f1 = unpack_e4m3((unsigned short)(rB.x >> 16));
                float2 f2 = unpack_e4m3((unsigned short)(rB.y & 0xffff));
                float2 f3 = unpack_e4m3((unsigned short)(rB.y >> 16));
                acc[0] = fmaf(wB, f0.x, acc[0]); acc[1] = fmaf(wB, f0.y, acc[1]);
                acc[2] = fmaf(wB, f1.x, acc[2]); acc[3] = fmaf(wB, f1.y, acc[3]);
                acc[4] = fmaf(wB, f2.x, acc[4]); acc[5] = fmaf(wB, f2.y, acc[5]);
                acc[6] = fmaf(wB, f3.x, acc[6]); acc[7] = fmaf(wB, f3.y, acc[7]);
            }
        }
        if (j < cnt) {
            int sA = ssrc[wrp][j];
            uint2 rA = *(const uint2*)(g_h1q + (size_t)sA * F1 + c0);
            float wA = ((const float*)&sww[wrp][j])[head];
            float2 f0 = unpack_e4m3((unsigned short)(rA.x & 0xffff));
            float2 f1 = unpack_e4m3((unsigned short)(rA.x >> 16));
            float2 f2 = unpack_e4m3((unsigned short)(rA.y & 0xffff));
            float2 f3 = unpack_e4m3((unsigned short)(rA.y >> 16));
            acc[0] = fmaf(wA, f0.x, acc[0]); acc[1] = fmaf(wA, f0.y, acc[1]);
            acc[2] = fmaf(wA, f1.x, acc[2]); acc[3] = fmaf(wA, f1.y, acc[3]);
            acc[4] = fmaf(wA, f2.x, acc[4]); acc[5] = fmaf(wA, f2.y, acc[5]);
            acc[6] = fmaf(wA, f3.x, acc[6]); acc[7] = fmaf(wA, f3.y, acc[7]);
        }
        __syncwarp();
    }

    // reduce denominators (per head), broadcast back
#pragma unroll
    for (int s = 16; s >= 1; s >>= 1) {
        den0 += __shfl_down_sync(0xffffffffu, den0, s);
        den1 += __shfl_down_sync(0xffffffffu, den1, s);
        den2 += __shfl_down_sync(0xffffffffu, den2, s);
        den3 += __shfl_down_sync(0xffffffffu, den3, s);
    }
    den0 = __shfl_sync(0xffffffffu, den0, 0);
    den1 = __shfl_sync(0xffffffffu, den1, 0);
    den2 = __shfl_sync(0xffffffffu, den2, 0);
    den3 = __shfl_sync(0xffffffffu, den3, 0);
    float inv = 1.f / ((head == 0) ? den0 : (head == 1) ? den1 : (head == 2) ? den2 : den3);

    float z[OUTCH];
#pragma unroll
    for (int j = 0; j < OUTCH; j++) z[j] = 0.f;
#pragma unroll
    for (int k = 0; k < 8; k++) {
        float t = fmaf(acc[k], inv, b1s[c0 + k]);
        t = t > 0.f ? t : expm1f(t);      // elu
#pragma unroll
        for (int j = 0; j < OUTCH; j++) z[j] = fmaf(t, W2s[(c0 + k) * OUTCH + j], z[j]);
    }
#pragma unroll
    for (int j = 0; j < OUTCH; j++)
#pragma unroll
        for (int s = 16; s >= 1; s >>= 1)
            z[j] += __shfl_down_sync(0xffffffffu, z[j], s);

    if (lane == 0) {
        float as = 0.f, ad = 0.f;
#pragma unroll
        for (int j = 0; j < OUTCH; j++) { as = fmaf(z[j], as2[j], as); ad = fmaf(z[j], ad2[j], ad); }
        float4* o = (float4*)(g_h2 + (size_t)n * 8);
        o[0] = make_float4(z[0], z[1], z[2], z[3]);
        o[1] = make_float4(z[4], z[5], as, ad);   // [h4, h5, al_src2, al_dst2]
    }
}

// ---------------- layer-2 aggregation + log_softmax (8 lanes per dst) ----------------
__global__ void __launch_bounds__(256) k_agg2(
    const float* __restrict__ b2, float* __restrict__ out, int N)
{
    int n = (blockIdx.x * blockDim.x + threadIdx.x) >> 3;
    if (n >= N) return;
    int sl = threadIdx.x & 7;
    int start = g_offs[n], end = g_offs[n + 1];

    float ald = g_h2[(size_t)n * 8 + 7];
    float acc[OUTCH] = {0.f, 0.f, 0.f, 0.f, 0.f, 0.f};
    float den = 0.f;

    for (int idx = start + sl; idx < end; idx += 8) {
        int src = g_sorted[idx];
        const float4* hp = (const float4*)(g_h2 + (size_t)src * 8);
        float4 a = hp[0];
        float4 b = hp[1];                  // [h4, h5, al_src, al_dst]
        float w = __expf(lrelu(b.z + ald));
        acc[0] = fmaf(w, a.x, acc[0]); acc[1] = fmaf(w, a.y, acc[1]);
        acc[2] = fmaf(w, a.z, acc[2]); acc[3] = fmaf(w, a.w, acc[3]);
        acc[4] = fmaf(w, b.x, acc[4]); acc[5] = fmaf(w, b.y, acc[5]);
        den += w;
    }
#pragma unroll
    for (int s = 4; s >= 1; s >>= 1) {
#pragma unroll
        for (int j = 0; j < OUTCH; j++) acc[j] += __shfl_down_sync(0xffffffffu, acc[j], s, 8);
        den += __shfl_down_sync(0xffffffffu, den, s, 8);
    }
    if (sl == 0) {
        float inv = 1.f / den;
        float y[OUTCH], mx = -1e30f;
#pragma unroll
        for (int j = 0; j < OUTCH; j++) {
            y[j] = fmaf(acc[j], inv, b2[j]);
            mx = fmaxf(mx, y[j]);
        }
        float s = 0.f;
#pragma unroll
        for (int j = 0; j < OUTCH; j++) s += expf(y[j] - mx);
        float l = mx + logf(s);
#pragma unroll
        for (int j = 0; j < OUTCH; j++) out[(size_t)n * OUTCH + j] = y[j] - l;
    }
}

extern "C" void kernel_launch(void* const* d_in, const int* in_sizes, int n_in,
                              void* d_out, int out_size)
{
    const float* x      = (const float*)d_in[0];
    const void*  ei     = d_in[1];
    const float* W1     = (const float*)d_in[2];
    const float* a_src1 = (const float*)d_in[3];
    const float* a_dst1 = (const float*)d_in[4];
    const float* b1     = (const float*)d_in[5];
    const float* W2     = (const float*)d_in[6];
    const float* a_src2 = (const float*)d_in[7];
    const float* a_dst2 = (const float*)d_in[8];
    const float* b2     = (const float*)d_in[9];
    float*       out    = (float*)d_out;

    int N  = in_sizes[0] / INCH;
    int E  = in_sizes[1] / 2;
    int TE = E + N;
    int NB = (N + 255) / 256;

    void* p_cnt;
    cudaGetSymbolAddress(&p_cnt, g_cnt);
    cudaMemsetAsync(p_cnt, 0, (size_t)N * sizeof(int), 0);

    k_detect<<<1, 32>>>(ei, E, N);
    k_node1<<<(N + 7) / 8, 256>>>(x, W1, a_src1, a_dst1, N);
    k_hist<<<(TE + 255) / 256, 256>>>(ei, E, N);
    k_scanA<<<NB, 256>>>(N);
    k_scanB<<<1, 256>>>(NB, N);
    k_scanC<<<NB, 256>>>(N);
    k_scatter<<<(TE + 255) / 256, 256>>>(E, N);
    k_agg1n2<<<(N * 32 + 255) / 256, 256>>>(b1, W2, a_src2, a_dst2, N);
    k_agg2<<<(N * 8 + 255) / 256, 256>>>(b2, out, N);
}

// round 7
// speedup vs baseline: 2.7826x; 1.0301x over previous
#include <cuda_runtime.h>
#include <cuda_fp16.h>
#include <math.h>

#define NMAX    50000
#define EMAX    1700000   // E + N upper bound
#define INCH    7
#define HID     64
#define HEADS   4
#define F1      (HEADS*HID)   // 256
#define OUTCH   6
#define NB_MAX  256       // ceil(NMAX/256) = 196 <= 256

// Scratch (static __device__ — allocation is forbidden)
__device__ __align__(16) unsigned char g_h1q[NMAX * F1]; // layer-1 features, fp8 e4m3
__device__ __align__(16) float g_al1[NMAX * 8];   // [al_src1[4], al_dst1[4]] (fp32)
__device__ __align__(16) float g_h2 [NMAX * 8];   // [h2[6], al_src2, al_dst2]
__device__ int g_cnt   [NMAX];
__device__ int g_offs  [NMAX + 1];
__device__ int g_cursor[NMAX];
__device__ int g_sorted[EMAX];                    // src ids grouped by dst
__device__ int g_src32 [EMAX];
__device__ int g_dst32 [EMAX];
__device__ int g_bsum  [NB_MAX];
__device__ int g_boff  [NB_MAX];
__device__ int g_is64;

__device__ __forceinline__ float lrelu(float v) { return v > 0.f ? v : 0.2f * v; }

__device__ __forceinline__ unsigned short pack_e4m3(float lo, float hi) {
    unsigned short r;
    asm("cvt.rn.satfinite.e4m3x2.f32 %0, %1, %2;" : "=h"(r) : "f"(hi), "f"(lo));
    return r;
}
__device__ __forceinline__ float2 unpack_e4m3(unsigned short v) {
    unsigned int h;
    asm("cvt.rn.f16x2.e4m3x2 %0, %1;" : "=r"(h) : "h"(v));
    __half2 hh = *(__half2*)&h;
    return __half22float2(hh);
}

// accumulate one fp8 row (uint2) with weight w into acc[8]
__device__ __forceinline__ void acc_row(float* acc, uint2 r, float w) {
    float2 f0 = unpack_e4m3((unsigned short)(r.x & 0xffff));
    float2 f1 = unpack_e4m3((unsigned short)(r.x >> 16));
    float2 f2 = unpack_e4m3((unsigned short)(r.y & 0xffff));
    float2 f3 = unpack_e4m3((unsigned short)(r.y >> 16));
    acc[0] = fmaf(w, f0.x, acc[0]); acc[1] = fmaf(w, f0.y, acc[1]);
    acc[2] = fmaf(w, f1.x, acc[2]); acc[3] = fmaf(w, f1.y, acc[3]);
    acc[4] = fmaf(w, f2.x, acc[4]); acc[5] = fmaf(w, f2.y, acc[5]);
    acc[6] = fmaf(w, f3.x, acc[6]); acc[7] = fmaf(w, f3.y, acc[7]);
}

__device__ __forceinline__ void get_edge64(const void* ei, int E, int e, int& src, int& dst) {
    if (g_is64) {
        const long long* p = (const long long*)ei;
        src = (int)p[e]; dst = (int)p[E + e];
    } else {
        const int* p = (const int*)ei;
        src = p[e]; dst = p[E + e];
    }
}

// ---------------- dtype detect ----------------
__global__ void k_detect(const void* ei, int E, int N) {
    if (threadIdx.x != 0 || blockIdx.x != 0) return;
    const long long* p = (const long long*)ei;
    int m = E < 256 ? E : 256;
    int ok = 1;
    for (int i = 0; i < m; i++) {
        long long v = p[i];
        if (v < 0 || v >= N) { ok = 0; break; }
    }
    g_is64 = ok;
}

// ---------------- CSR build: histogram + int32 conversion ----------------
__global__ void k_hist(const void* __restrict__ ei, int E, int N) {
    int e = blockIdx.x * blockDim.x + threadIdx.x;
    int total = E + N;
    if (e >= total) return;
    int dst;
    if (e < E) {
        int src;
        get_edge64(ei, E, e, src, dst);
        g_src32[e] = src;
        g_dst32[e] = dst;
    } else {
        dst = e - E;
    }
    atomicAdd(&g_cnt[dst], 1);
}

// ---------------- CSR scan A ----------------
__global__ void __launch_bounds__(256) k_scanA(int N) {
    int b = blockIdx.x, t = threadIdx.x;
    int i = b * 256 + t;
    int c = (i < N) ? g_cnt[i] : 0;
    int v = c;
#pragma unroll
    for (int s = 1; s < 32; s <<= 1) {
        int u = __shfl_up_sync(0xffffffffu, v, s);
        if ((t & 31) >= s) v += u;
    }
    __shared__ int wsum[8];
    if ((t & 31) == 31) wsum[t >> 5] = v;
    __syncthreads();
    if (t == 0) {
        int run = 0;
#pragma unroll
        for (int w = 0; w < 8; w++) { int x = wsum[w]; wsum[w] = run; run += x; }
        g_bsum[b] = run;
    }
    __syncthreads();
    if (i < N) g_offs[i] = v - c + wsum[t >> 5];
}

// ---------------- CSR scan B ----------------
__global__ void __launch_bounds__(256) k_scanB(int NB, int N) {
    int t = threadIdx.x;
    int c = (t < NB) ? g_bsum[t] : 0;
    int v = c;
#pragma unroll
    for (int s = 1; s < 32; s <<= 1) {
        int u = __shfl_up_sync(0xffffffffu, v, s);
        if ((t & 31) >= s) v += u;
    }
    __shared__ int wsum[8];
    if ((t & 31) == 31) wsum[t >> 5] = v;
    __syncthreads();
    if (t == 0) {
        int run = 0;
#pragma unroll
        for (int w = 0; w < 8; w++) { int x = wsum[w]; wsum[w] = run; run += x; }
    }
    __syncthreads();
    int incl = v + wsum[t >> 5];
    if (t < NB) g_boff[t] = incl - c;
    if (t == NB - 1) g_offs[N] = incl;
}

// ---------------- CSR scan C ----------------
__global__ void __launch_bounds__(256) k_scanC(int N) {
    int i = blockIdx.x * 256 + threadIdx.x;
    if (i >= N) return;
    int o = g_offs[i] + g_boff[blockIdx.x];
    g_offs[i] = o;
    g_cursor[i] = o;
}

// ---------------- CSR build: scatter ----------------
__global__ void k_scatter(int E, int N) {
    int e = blockIdx.x * blockDim.x + threadIdx.x;
    int total = E + N;
    if (e >= total) return;
    int src, dst;
    if (e < E) { src = g_src32[e]; dst = g_dst32[e]; }
    else       { src = dst = e - E; }
    int pos = atomicAdd(&g_cursor[dst], 1);
    g_sorted[pos] = src;
}

// ---------------- node transform 1 (warp per node) ----------------
__global__ void __launch_bounds__(256) k_node1(
    const float* __restrict__ x, const float* __restrict__ W1,
    const float* __restrict__ a_src1, const float* __restrict__ a_dst1, int N)
{
    __shared__ float W1s[INCH * F1];
    __shared__ float as1[F1], ad1[F1];
    int tid = threadIdx.x;
    for (int i = tid; i < INCH * F1; i += 256) W1s[i] = W1[i];
    as1[tid] = a_src1[tid];
    ad1[tid] = a_dst1[tid];
    __syncthreads();

    int n = blockIdx.x * 8 + (tid >> 5);
    if (n >= N) return;
    int lane = tid & 31;
    int c0 = lane * 8;
    int head = lane >> 3;

    float xv = (lane < INCH) ? x[n * INCH + lane] : 0.f;
    float h[8];
#pragma unroll
    for (int j = 0; j < 8; j++) h[j] = 0.f;
#pragma unroll
    for (int i = 0; i < INCH; i++) {
        float xi = __shfl_sync(0xffffffffu, xv, i);
#pragma unroll
        for (int j = 0; j < 8; j++) h[j] = fmaf(xi, W1s[i * F1 + c0 + j], h[j]);
    }
    unsigned short p0 = pack_e4m3(h[0], h[1]);
    unsigned short p1 = pack_e4m3(h[2], h[3]);
    unsigned short p2 = pack_e4m3(h[4], h[5]);
    unsigned short p3 = pack_e4m3(h[6], h[7]);
    uint2 pk;
    pk.x = (unsigned)p0 | ((unsigned)p1 << 16);
    pk.y = (unsigned)p2 | ((unsigned)p3 << 16);
    *(uint2*)(g_h1q + (size_t)n * F1 + c0) = pk;

    float ps = 0.f, pd = 0.f;
#pragma unroll
    for (int j = 0; j < 8; j++) {
        ps = fmaf(h[j], as1[c0 + j], ps);
        pd = fmaf(h[j], ad1[c0 + j], pd);
    }
#pragma unroll
    for (int s = 4; s >= 1; s >>= 1) {
        ps += __shfl_down_sync(0xffffffffu, ps, s, 8);
        pd += __shfl_down_sync(0xffffffffu, pd, s, 8);
    }
    if ((lane & 7) == 0) {
        g_al1[n * 8 + head]     = ps;
        g_al1[n * 8 + 4 + head] = pd;
    }
}

// ---------------- FUSED HEAVY: layer-1 agg + normalize + elu + @W2 + layer-2 logits ----------------
__global__ void __launch_bounds__(256) k_agg1n2(
    const float* __restrict__ b1, const float* __restrict__ W2,
    const float* __restrict__ a_src2, const float* __restrict__ a_dst2, int N)
{
    __shared__ float W2s[F1 * OUTCH];   // 6 KB
    __shared__ float b1s[F1];
    __shared__ float as2[OUTCH], ad2[OUTCH];
    __shared__ int    ssrc[8][32];
    __shared__ float4 sww [8][32];
    int tid = threadIdx.x;
    for (int i = tid; i < F1 * OUTCH; i += 256) W2s[i] = W2[i];
    b1s[tid] = b1[tid];
    if (tid < OUTCH) { as2[tid] = a_src2[tid]; ad2[tid] = a_dst2[tid]; }
    __syncthreads();

    int n = (blockIdx.x * blockDim.x + tid) >> 5;
    if (n >= N) return;
    int lane = tid & 31;
    int wrp = tid >> 5;
    int c0 = lane * 8;
    int head = lane >> 3;
    int start = g_offs[n], end = g_offs[n + 1];

    const float4 d4 = *(const float4*)(g_al1 + (size_t)n * 8 + 4);
    float acc[8];
#pragma unroll
    for (int j = 0; j < 8; j++) acc[j] = 0.f;
    float den0 = 0.f, den1 = 0.f, den2 = 0.f, den3 = 0.f;

    for (int base = start; base < end; base += 32) {
        int cnt = min(32, end - base);
        if (lane < cnt) {
            int s = g_sorted[base + lane];
            float4 s4 = *(const float4*)(g_al1 + (size_t)s * 8);
            float w0 = __expf(lrelu(s4.x + d4.x));
            float w1 = __expf(lrelu(s4.y + d4.y));
            float w2 = __expf(lrelu(s4.z + d4.z));
            float w3 = __expf(lrelu(s4.w + d4.w));
            den0 += w0; den1 += w1; den2 += w2; den3 += w3;
            ssrc[wrp][lane] = s;
            sww [wrp][lane] = make_float4(w0, w1, w2, w3);
        }
        __syncwarp();
        int j = 0;
        for (; j + 4 <= cnt; j += 4) {
            // issue 4 independent gathers before consuming any
            int s0 = ssrc[wrp][j], s1 = ssrc[wrp][j+1], s2 = ssrc[wrp][j+2], s3 = ssrc[wrp][j+3];
            uint2 r0 = *(const uint2*)(g_h1q + (size_t)s0 * F1 + c0);
            uint2 r1 = *(const uint2*)(g_h1q + (size_t)s1 * F1 + c0);
            uint2 r2 = *(const uint2*)(g_h1q + (size_t)s2 * F1 + c0);
            uint2 r3 = *(const uint2*)(g_h1q + (size_t)s3 * F1 + c0);
            float w0 = ((const float*)&sww[wrp][j  ])[head];
            float w1 = ((const float*)&sww[wrp][j+1])[head];
            float w2 = ((const float*)&sww[wrp][j+2])[head];
            float w3 = ((const float*)&sww[wrp][j+3])[head];
            acc_row(acc, r0, w0);
            acc_row(acc, r1, w1);
            acc_row(acc, r2, w2);
            acc_row(acc, r3, w3);
        }
        for (; j < cnt; j++) {
            int sA = ssrc[wrp][j];
            uint2 rA = *(const uint2*)(g_h1q + (size_t)sA * F1 + c0);
            float wA = ((const float*)&sww[wrp][j])[head];
            acc_row(acc, rA, wA);
        }
        __syncwarp();
    }

#pragma unroll
    for (int s = 16; s >= 1; s >>= 1) {
        den0 += __shfl_down_sync(0xffffffffu, den0, s);
        den1 += __shfl_down_sync(0xffffffffu, den1, s);
        den2 += __shfl_down_sync(0xffffffffu, den2, s);
        den3 += __shfl_down_sync(0xffffffffu, den3, s);
    }
    den0 = __shfl_sync(0xffffffffu, den0, 0);
    den1 = __shfl_sync(0xffffffffu, den1, 0);
    den2 = __shfl_sync(0xffffffffu, den2, 0);
    den3 = __shfl_sync(0xffffffffu, den3, 0);
    float inv = 1.f / ((head == 0) ? den0 : (head == 1) ? den1 : (head == 2) ? den2 : den3);

    float z[OUTCH];
#pragma unroll
    for (int j = 0; j < OUTCH; j++) z[j] = 0.f;
#pragma unroll
    for (int k = 0; k < 8; k++) {
        float t = fmaf(acc[k], inv, b1s[c0 + k]);
        t = t > 0.f ? t : expm1f(t);      // elu
#pragma unroll
        for (int j = 0; j < OUTCH; j++) z[j] = fmaf(t, W2s[(c0 + k) * OUTCH + j], z[j]);
    }
#pragma unroll
    for (int j = 0; j < OUTCH; j++)
#pragma unroll
        for (int s = 16; s >= 1; s >>= 1)
            z[j] += __shfl_down_sync(0xffffffffu, z[j], s);

    if (lane == 0) {
        float as = 0.f, ad = 0.f;
#pragma unroll
        for (int j = 0; j < OUTCH; j++) { as = fmaf(z[j], as2[j], as); ad = fmaf(z[j], ad2[j], ad); }
        float4* o = (float4*)(g_h2 + (size_t)n * 8);
        o[0] = make_float4(z[0], z[1], z[2], z[3]);
        o[1] = make_float4(z[4], z[5], as, ad);   // [h4, h5, al_src2, al_dst2]
    }
}

// ---------------- layer-2 aggregation + log_softmax (8 lanes per dst, 2-edge unroll) ----------------
__global__ void __launch_bounds__(256) k_agg2(
    const float* __restrict__ b2, float* __restrict__ out, int N)
{
    int n = (blockIdx.x * blockDim.x + threadIdx.x) >> 3;
    if (n >= N) return;
    int sl = threadIdx.x & 7;
    int start = g_offs[n], end = g_offs[n + 1];

    float ald = g_h2[(size_t)n * 8 + 7];
    float acc[OUTCH] = {0.f, 0.f, 0.f, 0.f, 0.f, 0.f};
    float den = 0.f;

    int idx = start + sl;
    // 2 edges in flight per lane
    for (; idx + 8 < end; idx += 16) {
        int srcA = g_sorted[idx];
        int srcB = g_sorted[idx + 8];
        const float4* hA = (const float4*)(g_h2 + (size_t)srcA * 8);
        const float4* hB = (const float4*)(g_h2 + (size_t)srcB * 8);
        float4 aA = hA[0], bA = hA[1];
        float4 aB = hB[0], bB = hB[1];
        float wA = __expf(lrelu(bA.z + ald));
        float wB = __expf(lrelu(bB.z + ald));
        acc[0] = fmaf(wA, aA.x, acc[0]); acc[1] = fmaf(wA, aA.y, acc[1]);
        acc[2] = fmaf(wA, aA.z, acc[2]); acc[3] = fmaf(wA, aA.w, acc[3]);
        acc[4] = fmaf(wA, bA.x, acc[4]); acc[5] = fmaf(wA, bA.y, acc[5]);
        den += wA;
        acc[0] = fmaf(wB, aB.x, acc[0]); acc[1] = fmaf(wB, aB.y, acc[1]);
        acc[2] = fmaf(wB, aB.z, acc[2]); acc[3] = fmaf(wB, aB.w, acc[3]);
        acc[4] = fmaf(wB, bB.x, acc[4]); acc[5] = fmaf(wB, bB.y, acc[5]);
        den += wB;
    }
    if (idx < end) {
        int src = g_sorted[idx];
        const float4* hp = (const float4*)(g_h2 + (size_t)src * 8);
        float4 a = hp[0], b = hp[1];
        float w = __expf(lrelu(b.z + ald));
        acc[0] = fmaf(w, a.x, acc[0]); acc[1] = fmaf(w, a.y, acc[1]);
        acc[2] = fmaf(w, a.z, acc[2]); acc[3] = fmaf(w, a.w, acc[3]);
        acc[4] = fmaf(w, b.x, acc[4]); acc[5] = fmaf(w, b.y, acc[5]);
        den += w;
    }
#pragma unroll
    for (int s = 4; s >= 1; s >>= 1) {
#pragma unroll
        for (int j = 0; j < OUTCH; j++) acc[j] += __shfl_down_sync(0xffffffffu, acc[j], s, 8);
        den += __shfl_down_sync(0xffffffffu, den, s, 8);
    }
    if (sl == 0) {
        float inv = 1.f / den;
        float y[OUTCH], mx = -1e30f;
#pragma unroll
        for (int j = 0; j < OUTCH; j++) {
            y[j] = fmaf(acc[j], inv, b2[j]);
            mx = fmaxf(mx, y[j]);
        }
        float s = 0.f;
#pragma unroll
        for (int j = 0; j < OUTCH; j++) s += expf(y[j] - mx);
        float l = mx + logf(s);
#pragma unroll
        for (int j = 0; j < OUTCH; j++) out[(size_t)n * OUTCH + j] = y[j] - l;
    }
}

extern "C" void kernel_launch(void* const* d_in, const int* in_sizes, int n_in,
                              void* d_out, int out_size)
{
    const float* x      = (const float*)d_in[0];
    const void*  ei     = d_in[1];
    const float* W1     = (const float*)d_in[2];
    const float* a_src1 = (const float*)d_in[3];
    const float* a_dst1 = (const float*)d_in[4];
    const float* b1     = (const float*)d_in[5];
    const float* W2     = (const float*)d_in[6];
    const float* a_src2 = (const float*)d_in[7];
    const float* a_dst2 = (const float*)d_in[8];
    const float* b2     = (const float*)d_in[9];
    float*       out    = (float*)d_out;

    int N  = in_sizes[0] / INCH;
    int E  = in_sizes[1] / 2;
    int TE = E + N;
    int NB = (N + 255) / 256;

    void* p_cnt;
    cudaGetSymbolAddress(&p_cnt, g_cnt);
    cudaMemsetAsync(p_cnt, 0, (size_t)N * sizeof(int), 0);

    k_detect<<<1, 32>>>(ei, E, N);
    k_node1<<<(N + 7) / 8, 256>>>(x, W1, a_src1, a_dst1, N);
    k_hist<<<(TE + 255) / 256, 256>>>(ei, E, N);
    k_scanA<<<NB, 256>>>(N);
    k_scanB<<<1, 256>>>(NB, N);
    k_scanC<<<NB, 256>>>(N);
    k_scatter<<<(TE + 255) / 256, 256>>>(E, N);
    k_agg1n2<<<(N * 32 + 255) / 256, 256>>>(b1, W2, a_src2, a_dst2, N);
    k_agg2<<<(N * 8 + 255) / 256, 256>>>(b2, out, N);
}

// round 8
// speedup vs baseline: 2.8415x; 1.0212x over previous
#include <cuda_runtime.h>
#include <cuda_fp16.h>
#include <math.h>

#define NMAX    50000
#define EMAX    1700000   // E + N upper bound
#define INCH    7
#define HID     64
#define HEADS   4
#define F1      (HEADS*HID)   // 256
#define OUTCH   6
#define NB_MAX  256       // ceil(NMAX/256) = 196 <= 256

// Scratch (static __device__ — allocation is forbidden)
__device__ __align__(16) unsigned char g_h1q[NMAX * F1]; // layer-1 features, fp8 e4m3
__device__ __align__(16) float g_al1[NMAX * 8];   // [al_src1[4], al_dst1[4]] (fp32)
__device__ __align__(16) float g_h2 [NMAX * 8];   // [h2[6], al_src2, al_dst2]
__device__ int g_cnt   [NMAX];
__device__ int g_offs  [NMAX + 1];
__device__ int g_cursor[NMAX];
__device__ int g_sorted[EMAX];                    // src ids grouped by dst
__device__ int g_src32 [EMAX];
__device__ int g_dst32 [EMAX];
__device__ int g_pub   [NB_MAX];                  // decoupled-lookback: aggregate+1, 0=not ready

__device__ __forceinline__ float lrelu(float v) { return v > 0.f ? v : 0.2f * v; }

__device__ __forceinline__ unsigned short pack_e4m3(float lo, float hi) {
    unsigned short r;
    asm("cvt.rn.satfinite.e4m3x2.f32 %0, %1, %2;" : "=h"(r) : "f"(hi), "f"(lo));
    return r;
}
__device__ __forceinline__ float2 unpack_e4m3(unsigned short v) {
    unsigned int h;
    asm("cvt.rn.f16x2.e4m3x2 %0, %1;" : "=r"(h) : "h"(v));
    __half2 hh = *(__half2*)&h;
    return __half22float2(hh);
}

__device__ __forceinline__ void acc_row(float* acc, uint2 r, float w) {
    float2 f0 = unpack_e4m3((unsigned short)(r.x & 0xffff));
    float2 f1 = unpack_e4m3((unsigned short)(r.x >> 16));
    float2 f2 = unpack_e4m3((unsigned short)(r.y & 0xffff));
    float2 f3 = unpack_e4m3((unsigned short)(r.y >> 16));
    acc[0] = fmaf(w, f0.x, acc[0]); acc[1] = fmaf(w, f0.y, acc[1]);
    acc[2] = fmaf(w, f1.x, acc[2]); acc[3] = fmaf(w, f1.y, acc[3]);
    acc[4] = fmaf(w, f2.x, acc[4]); acc[5] = fmaf(w, f2.y, acc[5]);
    acc[6] = fmaf(w, f3.x, acc[6]); acc[7] = fmaf(w, f3.y, acc[7]);
}

// ---------------- node transform 1 (warp per node) + zero cnt/pub ----------------
__global__ void __launch_bounds__(256) k_node1(
    const float* __restrict__ x, const float* __restrict__ W1,
    const float* __restrict__ a_src1, const float* __restrict__ a_dst1, int N)
{
    int tid = threadIdx.x;
    // fold the CSR-counter memset into this first kernel
    {
        int nb = (N + 255) >> 8;
        if ((int)blockIdx.x < nb) {
            int i = blockIdx.x * 256 + tid;
            if (i < N) g_cnt[i] = 0;
        } else if ((int)blockIdx.x == nb) {
            if (tid < NB_MAX) g_pub[tid] = 0;
        }
    }

    __shared__ float W1s[INCH * F1];
    __shared__ float as1[F1], ad1[F1];
    for (int i = tid; i < INCH * F1; i += 256) W1s[i] = W1[i];
    as1[tid] = a_src1[tid];
    ad1[tid] = a_dst1[tid];
    __syncthreads();

    int n = blockIdx.x * 8 + (tid >> 5);
    if (n >= N) return;
    int lane = tid & 31;
    int c0 = lane * 8;
    int head = lane >> 3;

    float xv = (lane < INCH) ? x[n * INCH + lane] : 0.f;
    float h[8];
#pragma unroll
    for (int j = 0; j < 8; j++) h[j] = 0.f;
#pragma unroll
    for (int i = 0; i < INCH; i++) {
        float xi = __shfl_sync(0xffffffffu, xv, i);
#pragma unroll
        for (int j = 0; j < 8; j++) h[j] = fmaf(xi, W1s[i * F1 + c0 + j], h[j]);
    }
    unsigned short p0 = pack_e4m3(h[0], h[1]);
    unsigned short p1 = pack_e4m3(h[2], h[3]);
    unsigned short p2 = pack_e4m3(h[4], h[5]);
    unsigned short p3 = pack_e4m3(h[6], h[7]);
    uint2 pk;
    pk.x = (unsigned)p0 | ((unsigned)p1 << 16);
    pk.y = (unsigned)p2 | ((unsigned)p3 << 16);
    *(uint2*)(g_h1q + (size_t)n * F1 + c0) = pk;

    float ps = 0.f, pd = 0.f;
#pragma unroll
    for (int j = 0; j < 8; j++) {
        ps = fmaf(h[j], as1[c0 + j], ps);
        pd = fmaf(h[j], ad1[c0 + j], pd);
    }
#pragma unroll
    for (int s = 4; s >= 1; s >>= 1) {
        ps += __shfl_down_sync(0xffffffffu, ps, s, 8);
        pd += __shfl_down_sync(0xffffffffu, pd, s, 8);
    }
    if ((lane & 7) == 0) {
        g_al1[n * 8 + head]     = ps;
        g_al1[n * 8 + 4 + head] = pd;
    }
}

// ---------------- CSR build: histogram + int32 conversion + inline dtype detect ----------------
__global__ void __launch_bounds__(256) k_hist(const void* __restrict__ ei, int E, int N) {
    int tid = threadIdx.x;
    // block-uniform dtype detect: 64 parallel samples, AND-reduced across the block
    int ok = 1;
    int m = (E * 2 < 64) ? E * 2 : 64;
    if (tid < m) {
        long long v = ((const long long*)ei)[tid];
        ok = (v >= 0 && v < N);
    }
    int is64 = __syncthreads_and(ok);

    int e = blockIdx.x * blockDim.x + tid;
    int total = E + N;
    if (e >= total) return;
    int dst;
    if (e < E) {
        int src;
        if (is64) {
            const long long* p = (const long long*)ei;
            src = (int)p[e]; dst = (int)p[E + e];
        } else {
            const int* p = (const int*)ei;
            src = p[e]; dst = p[E + e];
        }
        g_src32[e] = src;
        g_dst32[e] = dst;
    } else {
        dst = e - E;
    }
    atomicAdd(&g_cnt[dst], 1);
}

// ---------------- CSR scan: single kernel, decoupled lookback ----------------
__global__ void __launch_bounds__(256) k_scan(int N, int NB) {
    int b = blockIdx.x, t = threadIdx.x;
    int i = b * 256 + t;
    int c = (i < N) ? g_cnt[i] : 0;
    int v = c;
#pragma unroll
    for (int s = 1; s < 32; s <<= 1) {
        int u = __shfl_up_sync(0xffffffffu, v, s);
        if ((t & 31) >= s) v += u;
    }
    __shared__ int wsum[8];
    __shared__ int s_agg, s_base;
    if ((t & 31) == 31) wsum[t >> 5] = v;
    __syncthreads();
    if (t == 0) {
        int run = 0;
#pragma unroll
        for (int w = 0; w < 8; w++) { int x = wsum[w]; wsum[w] = run; run += x; }
        s_agg = run;
        atomicExch(&g_pub[b], run + 1);   // publish aggregate (ready = nonzero)
    }
    __syncthreads();
    int loc = v - c + wsum[t >> 5];

    // lookback: thread t polls predecessor t's aggregate
    int pred = 0;
    if (t < b) {
        int x;
        while ((x = atomicAdd(&g_pub[t], 0)) == 0) {}
        pred = x - 1;
    }
#pragma unroll
    for (int s = 16; s >= 1; s >>= 1) pred += __shfl_down_sync(0xffffffffu, pred, s);
    __shared__ int psum[8];
    if ((t & 31) == 0) psum[t >> 5] = pred;
    __syncthreads();
    if (t == 0) {
        int base = 0;
#pragma unroll
        for (int w = 0; w < 8; w++) base += psum[w];
        s_base = base;
    }
    __syncthreads();
    int o = loc + s_base;
    if (i < N) { g_offs[i] = o; g_cursor[i] = o; }
    if (b == NB - 1 && t == 0) g_offs[N] = s_base + s_agg;
}

// ---------------- CSR build: scatter ----------------
__global__ void k_scatter(int E, int N) {
    int e = blockIdx.x * blockDim.x + threadIdx.x;
    int total = E + N;
    if (e >= total) return;
    int src, dst;
    if (e < E) { src = g_src32[e]; dst = g_dst32[e]; }
    else       { src = dst = e - E; }
    int pos = atomicAdd(&g_cursor[dst], 1);
    g_sorted[pos] = src;
}

// ---------------- FUSED HEAVY: layer-1 agg + normalize + elu + @W2 + layer-2 logits ----------------
__global__ void __launch_bounds__(256) k_agg1n2(
    const float* __restrict__ b1, const float* __restrict__ W2,
    const float* __restrict__ a_src2, const float* __restrict__ a_dst2, int N)
{
    __shared__ float W2s[F1 * OUTCH];   // 6 KB
    __shared__ float b1s[F1];
    __shared__ float as2[OUTCH], ad2[OUTCH];
    __shared__ int    ssrc[8][32];
    __shared__ float4 sww [8][32];
    int tid = threadIdx.x;
    for (int i = tid; i < F1 * OUTCH; i += 256) W2s[i] = W2[i];
    b1s[tid] = b1[tid];
    if (tid < OUTCH) { as2[tid] = a_src2[tid]; ad2[tid] = a_dst2[tid]; }
    __syncthreads();

    int n = (blockIdx.x * blockDim.x + tid) >> 5;
    if (n >= N) return;
    int lane = tid & 31;
    int wrp = tid >> 5;
    int c0 = lane * 8;
    int head = lane >> 3;
    int start = g_offs[n], end = g_offs[n + 1];

    const float4 d4 = *(const float4*)(g_al1 + (size_t)n * 8 + 4);
    float acc[8];
#pragma unroll
    for (int j = 0; j < 8; j++) acc[j] = 0.f;
    float den0 = 0.f, den1 = 0.f, den2 = 0.f, den3 = 0.f;

    for (int base = start; base < end; base += 32) {
        int cnt = min(32, end - base);
        if (lane < cnt) {
            int s = g_sorted[base + lane];
            float4 s4 = *(const float4*)(g_al1 + (size_t)s * 8);
            float w0 = __expf(lrelu(s4.x + d4.x));
            float w1 = __expf(lrelu(s4.y + d4.y));
            float w2 = __expf(lrelu(s4.z + d4.z));
            float w3 = __expf(lrelu(s4.w + d4.w));
            den0 += w0; den1 += w1; den2 += w2; den3 += w3;
            ssrc[wrp][lane] = s;
            sww [wrp][lane] = make_float4(w0, w1, w2, w3);
        }
        __syncwarp();
        int j = 0;
        for (; j + 4 <= cnt; j += 4) {
            int s0 = ssrc[wrp][j], s1 = ssrc[wrp][j+1], s2 = ssrc[wrp][j+2], s3 = ssrc[wrp][j+3];
            uint2 r0 = *(const uint2*)(g_h1q + (size_t)s0 * F1 + c0);
            uint2 r1 = *(const uint2*)(g_h1q + (size_t)s1 * F1 + c0);
            uint2 r2 = *(const uint2*)(g_h1q + (size_t)s2 * F1 + c0);
            uint2 r3 = *(const uint2*)(g_h1q + (size_t)s3 * F1 + c0);
            float w0 = ((const float*)&sww[wrp][j  ])[head];
            float w1 = ((const float*)&sww[wrp][j+1])[head];
            float w2 = ((const float*)&sww[wrp][j+2])[head];
            float w3 = ((const float*)&sww[wrp][j+3])[head];
            acc_row(acc, r0, w0);
            acc_row(acc, r1, w1);
            acc_row(acc, r2, w2);
            acc_row(acc, r3, w3);
        }
        for (; j < cnt; j++) {
            int sA = ssrc[wrp][j];
            uint2 rA = *(const uint2*)(g_h1q + (size_t)sA * F1 + c0);
            float wA = ((const float*)&sww[wrp][j])[head];
            acc_row(acc, rA, wA);
        }
        __syncwarp();
    }

#pragma unroll
    for (int s = 16; s >= 1; s >>= 1) {
        den0 += __shfl_down_sync(0xffffffffu, den0, s);
        den1 += __shfl_down_sync(0xffffffffu, den1, s);
        den2 += __shfl_down_sync(0xffffffffu, den2, s);
        den3 += __shfl_down_sync(0xffffffffu, den3, s);
    }
    den0 = __shfl_sync(0xffffffffu, den0, 0);
    den1 = __shfl_sync(0xffffffffu, den1, 0);
    den2 = __shfl_sync(0xffffffffu, den2, 0);
    den3 = __shfl_sync(0xffffffffu, den3, 0);
    float inv = 1.f / ((head == 0) ? den0 : (head == 1) ? den1 : (head == 2) ? den2 : den3);

    float z[OUTCH];
#pragma unroll
    for (int j = 0; j < OUTCH; j++) z[j] = 0.f;
#pragma unroll
    for (int k = 0; k < 8; k++) {
        float t = fmaf(acc[k], inv, b1s[c0 + k]);
        t = t > 0.f ? t : expm1f(t);      // elu
#pragma unroll
        for (int j = 0; j < OUTCH; j++) z[j] = fmaf(t, W2s[(c0 + k) * OUTCH + j], z[j]);
    }
#pragma unroll
    for (int j = 0; j < OUTCH; j++)
#pragma unroll
        for (int s = 16; s >= 1; s >>= 1)
            z[j] += __shfl_down_sync(0xffffffffu, z[j], s);

    if (lane == 0) {
        float as = 0.f, ad = 0.f;
#pragma unroll
        for (int j = 0; j < OUTCH; j++) { as = fmaf(z[j], as2[j], as); ad = fmaf(z[j], ad2[j], ad); }
        float4* o = (float4*)(g_h2 + (size_t)n * 8);
        o[0] = make_float4(z[0], z[1], z[2], z[3]);
        o[1] = make_float4(z[4], z[5], as, ad);   // [h4, h5, al_src2, al_dst2]
    }
}

// ---------------- layer-2 aggregation + log_softmax (8 lanes per dst, 2-edge unroll) ----------------
__global__ void __launch_bounds__(256) k_agg2(
    const float* __restrict__ b2, float* __restrict__ out, int N)
{
    int n = (blockIdx.x * blockDim.x + threadIdx.x) >> 3;
    if (n >= N) return;
    int sl = threadIdx.x & 7;
    int start = g_offs[n], end = g_offs[n + 1];

    float ald = g_h2[(size_t)n * 8 + 7];
    float acc[OUTCH] = {0.f, 0.f, 0.f, 0.f, 0.f, 0.f};
    float den = 0.f;

    int idx = start + sl;
    for (; idx + 8 < end; idx += 16) {
        int srcA = g_sorted[idx];
        int srcB = g_sorted[idx + 8];
        const float4* hA = (const float4*)(g_h2 + (size_t)srcA * 8);
        const float4* hB = (const float4*)(g_h2 + (size_t)srcB * 8);
        float4 aA = hA[0], bA = hA[1];
        float4 aB = hB[0], bB = hB[1];
        float wA = __expf(lrelu(bA.z + ald));
        float wB = __expf(lrelu(bB.z + ald));
        acc[0] = fmaf(wA, aA.x, acc[0]); acc[1] = fmaf(wA, aA.y, acc[1]);
        acc[2] = fmaf(wA, aA.z, acc[2]); acc[3] = fmaf(wA, aA.w, acc[3]);
        acc[4] = fmaf(wA, bA.x, acc[4]); acc[5] = fmaf(wA, bA.y, acc[5]);
        den += wA;
        acc[0] = fmaf(wB, aB.x, acc[0]); acc[1] = fmaf(wB, aB.y, acc[1]);
        acc[2] = fmaf(wB, aB.z, acc[2]); acc[3] = fmaf(wB, aB.w, acc[3]);
        acc[4] = fmaf(wB, bB.x, acc[4]); acc[5] = fmaf(wB, bB.y, acc[5]);
        den += wB;
    }
    if (idx < end) {
        int src = g_sorted[idx];
        const float4* hp = (const float4*)(g_h2 + (size_t)src * 8);
        float4 a = hp[0], b = hp[1];
        float w = __expf(lrelu(b.z + ald));
        acc[0] = fmaf(w, a.x, acc[0]); acc[1] = fmaf(w, a.y, acc[1]);
        acc[2] = fmaf(w, a.z, acc[2]); acc[3] = fmaf(w, a.w, acc[3]);
        acc[4] = fmaf(w, b.x, acc[4]); acc[5] = fmaf(w, b.y, acc[5]);
        den += w;
    }
#pragma unroll
    for (int s = 4; s >= 1; s >>= 1) {
#pragma unroll
        for (int j = 0; j < OUTCH; j++) acc[j] += __shfl_down_sync(0xffffffffu, acc[j], s, 8);
        den += __shfl_down_sync(0xffffffffu, den, s, 8);
    }
    if (sl == 0) {
        float inv = 1.f / den;
        float y[OUTCH], mx = -1e30f;
#pragma unroll
        for (int j = 0; j < OUTCH; j++) {
            y[j] = fmaf(acc[j], inv, b2[j]);
            mx = fmaxf(mx, y[j]);
        }
        float s = 0.f;
#pragma unroll
        for (int j = 0; j < OUTCH; j++) s += expf(y[j] - mx);
        float l = mx + logf(s);
#pragma unroll
        for (int j = 0; j < OUTCH; j++) out[(size_t)n * OUTCH + j] = y[j] - l;
    }
}

extern "C" void kernel_launch(void* const* d_in, const int* in_sizes, int n_in,
                              void* d_out, int out_size)
{
    const float* x      = (const float*)d_in[0];
    const void*  ei     = d_in[1];
    const float* W1     = (const float*)d_in[2];
    const float* a_src1 = (const float*)d_in[3];
    const float* a_dst1 = (const float*)d_in[4];
    const float* b1     = (const float*)d_in[5];
    const float* W2     = (const float*)d_in[6];
    const float* a_src2 = (const float*)d_in[7];
    const float* a_dst2 = (const float*)d_in[8];
    const float* b2     = (const float*)d_in[9];
    float*       out    = (float*)d_out;

    int N  = in_sizes[0] / INCH;
    int E  = in_sizes[1] / 2;
    int TE = E + N;
    int NB = (N + 255) / 256;

    k_node1<<<(N + 7) / 8, 256>>>(x, W1, a_src1, a_dst1, N);    // also zeros cnt/pub
    k_hist<<<(TE + 255) / 256, 256>>>(ei, E, N);
    k_scan<<<NB, 256>>>(N, NB);
    k_scatter<<<(TE + 255) / 256, 256>>>(E, N);
    k_agg1n2<<<(N * 32 + 255) / 256, 256>>>(b1, W2, a_src2, a_dst2, N);
    k_agg2<<<(N * 8 + 255) / 256, 256>>>(b2, out, N);
}